// round 12
// baseline (speedup 1.0000x reference)
#include <cuda_runtime.h>
#include <math.h>
#include <stdint.h>

// Problem constants
#define BB 2
#define CC 128
#define NN 6000
#define MM 1500
#define HH 4
#define DHH 32
#define BH (BB*HH)
#define NSPLIT 4

// ---------------- scratch (static device globals; no allocation) ----------------
__device__ float g_Q  [BB*CC*NN];
__device__ float g_K  [BB*CC*NN];
__device__ float g_V  [BB*CC*NN];
__device__ float g_AO [BB*CC*NN];
__device__ float g_Hb [BB*2*CC*NN];
__device__ float g_F1 [BB*CC*MM];
__device__ float g_F2 [BB*CC*MM];
__device__ float g_XH [BB*CC*NN];
__device__ float g_T1 [BB*64*NN];
__device__ float g_T2 [BB*16*NN];
__device__ float g_T3 [BB*4*NN];
// split-KV partials
__device__ float g_OP [NSPLIT*BH*DHH*NN];
__device__ float g_MP [NSPLIT*BH*NN];
__device__ float g_LP [NSPLIT*BH*NN];
// fused Wc1' (K-major): WF[l][c][o]
__device__ float g_WF [3*2*CC*2*CC];
__device__ float g_BF [3*2*CC];
// transposed weights (K-major): Wq(3),Wk(3),Wv(3) 128x128; Wc2(3) 256x128; iW1 128x64
#define WT_Q   0
#define WT_K   49152
#define WT_V   98304
#define WT_C2  147456
#define WT_I1  245760
#define WT_TOT 253952
__device__ float g_WT [WT_TOT];

// ---------------- tf32 helpers ----------------
__device__ __forceinline__ uint32_t f2tf(float f) {
    uint32_t u;
    asm("cvt.rna.tf32.f32 %0, %1;" : "=r"(u) : "f"(f));
    return u;
}
__device__ __forceinline__ float tfb(float f) { return __uint_as_float(f2tf(f)); }

__device__ __forceinline__ void mma8(float* d, const uint32_t* a, const uint32_t* b) {
    asm volatile("mma.sync.aligned.m16n8k8.row.col.f32.tf32.tf32.f32 "
                 "{%0,%1,%2,%3}, {%4,%5,%6,%7}, {%8,%9}, {%0,%1,%2,%3};\n"
                 : "+f"(d[0]), "+f"(d[1]), "+f"(d[2]), "+f"(d[3])
                 : "r"(a[0]), "r"(a[1]), "r"(a[2]), "r"(a[3]),
                   "r"(b[0]), "r"(b[1]));
}

__device__ __forceinline__ uint32_t smem_u32(const void* p) {
    uint32_t a;
    asm("{ .reg .u64 t; cvta.to.shared.u64 t, %1; cvt.u32.u64 %0, t; }" : "=r"(a) : "l"(p));
    return a;
}
__device__ __forceinline__ void cp16(uint32_t dst, const void* src, uint32_t ssz) {
    asm volatile("cp.async.ca.shared.global [%0], [%1], 16, %2;"
                 :: "r"(dst), "l"(src), "r"(ssz));
}

// ---------------- weight prep kernels ----------------
__global__ void transpose_all(const float* __restrict__ Wq, const float* __restrict__ Wk,
                              const float* __restrict__ Wv, const float* __restrict__ Wc2,
                              const float* __restrict__ iW1, float* __restrict__ WT)
{
    int idx = blockIdx.x * blockDim.x + threadIdx.x;
    if (idx >= WT_TOT) return;
    float v;
    if (idx < WT_C2) {                      // q,k,v: 3 segs x 3 layers x 128x128
        int seg = idx / 49152;
        int r   = idx % 49152;
        int l   = r / 16384;
        int e   = r % 16384;
        int c   = e >> 7, o = e & 127;      // WT[l][c][o]
        const float* Wsrc = (seg == 0) ? Wq : ((seg == 1) ? Wk : Wv);
        v = Wsrc[l * 16384 + o * 128 + c];
    } else if (idx < WT_I1) {               // Wc2: 3 layers x 256(k) x 128(o)
        int r = idx - WT_C2;
        int l = r / 32768;
        int e = r % 32768;
        int c = e >> 7, o = e & 127;
        v = Wc2[l * 32768 + o * 256 + c];
    } else {                                // iW1: 128(k) x 64(o)
        int e = idx - WT_I1;
        int c = e >> 6, o = e & 63;
        v = iW1[o * 128 + c];
    }
    WT[idx] = v;
}

__global__ void fuse_wc1(const float* __restrict__ Wc1, const float* __restrict__ Wm,
                         float* __restrict__ WF)
{
    int idx = blockIdx.x * blockDim.x + threadIdx.x;   // (l, o, c)
    if (idx >= 3 * 256 * 256) return;
    int c = idx & 255;
    int o = (idx >> 8) & 255;
    int l = idx >> 16;
    const float* Wc1l = Wc1 + (size_t)l * 256 * 256;
    float v;
    if (c < CC) {
        v = Wc1l[o * 256 + c];
    } else {
        const float* wrow = Wc1l + o * 256 + CC;
        const float* wm   = Wm + (size_t)l * CC * CC;
        int cc = c - CC;
        float acc = 0.f;
#pragma unroll 4
        for (int k = 0; k < CC; k++) acc += wrow[k] * wm[k * CC + cc];
        v = acc;
    }
    WF[(size_t)l * 65536 + c * 256 + o] = v;   // K-major
}

__global__ void fuse_bc1(const float* __restrict__ Wc1, const float* __restrict__ bc1,
                         const float* __restrict__ bm, float* __restrict__ BF)
{
    int idx = blockIdx.x * blockDim.x + threadIdx.x;   // (l, o)
    if (idx >= 3 * 256) return;
    int o = idx & 255, l = idx >> 8;
    const float* wrow = Wc1 + (size_t)l * 256 * 256 + o * 256 + CC;
    const float* bml  = bm + l * CC;
    float acc = bc1[l * 256 + o];
#pragma unroll 4
    for (int k = 0; k < CC; k++) acc += wrow[k] * bml[k];
    BF[idx] = acc;
}

// ---------------- fp32 GEMM for 1x1 conv: cp.async double-buffered ----------------
// WT is K-major: WT[k*Cout + o]. CTA tile 64(out) x 64(n), K chunks of 32.
// 128 threads: tx=tid&15 (4 cols), ty=tid>>4 (8 rows).
#define CBK 32

__global__ void __launch_bounds__(128)
conv_gemm(const float* __restrict__ WT, const float* __restrict__ bias,
          const float* __restrict__ X1, const float* __restrict__ X2, int split,
          float* __restrict__ Y, float* __restrict__ Ypre,
          int Cout, int Cin, int Nlen,
          const float* __restrict__ scale, const float* __restrict__ shift,
          int do_relu, const float* __restrict__ resid, int round_out)
{
    __shared__ __align__(16) float Ws[2][CBK][64];
    __shared__ __align__(16) float Xs[2][CBK][64];

    const int b   = blockIdx.z;
    const int om0 = blockIdx.y * 64;
    const int n0  = blockIdx.x * 64;
    const int tid = threadIdx.x;
    const int tx  = tid & 15;
    const int ty  = tid >> 4;

    float acc[8][4];
#pragma unroll
    for (int i = 0; i < 8; i++)
#pragma unroll
        for (int j = 0; j < 4; j++) acc[i][j] = 0.f;

    const int Ci2 = Cin - split;

    auto stage = [&](int k0, int buf) {
        // W: 32 k-rows x 16 float4 along o (always in-bounds: Cout%64==0, Cin%32==0)
#pragma unroll
        for (int i = tid; i < 32 * 16; i += 128) {
            int kk = i >> 4, o4 = (i & 15) * 4;
            cp16(smem_u32(&Ws[buf][kk][o4]), &WT[(size_t)(k0 + kk) * Cout + om0 + o4], 16);
        }
        // X: 32 k-rows x 16 float4 along n (zero-fill OOB cols)
#pragma unroll
        for (int i = tid; i < 32 * 16; i += 128) {
            int kk = i >> 4, n4 = (i & 15) * 4;
            int c = k0 + kk;
            int n = n0 + n4;
            int nc = (n < Nlen) ? n : 0;
            const float* src;
            if (c < split) src = &X1[((size_t)b * split + c) * Nlen + nc];
            else           src = &X2[((size_t)b * Ci2 + (c - split)) * Nlen + nc];
            cp16(smem_u32(&Xs[buf][kk][n4]), src, (n < Nlen) ? 16u : 0u);
        }
    };

    const int nch = Cin / CBK;
    stage(0, 0);
    asm volatile("cp.async.commit_group;");

    for (int ch = 0; ch < nch; ch++) {
        if (ch + 1 < nch) {
            stage((ch + 1) * CBK, (ch + 1) & 1);
            asm volatile("cp.async.commit_group;");
            asm volatile("cp.async.wait_group 1;");
        } else {
            asm volatile("cp.async.wait_group 0;");
        }
        __syncthreads();

        const float (*Wb)[64] = Ws[ch & 1];
        const float (*Xb)[64] = Xs[ch & 1];
#pragma unroll 8
        for (int kk = 0; kk < CBK; kk++) {
            float4 w0 = *(const float4*)&Wb[kk][ty * 8];
            float4 w1 = *(const float4*)&Wb[kk][ty * 8 + 4];
            float4 rx = *(const float4*)&Xb[kk][tx * 4];
            const float wv[8] = {w0.x, w0.y, w0.z, w0.w, w1.x, w1.y, w1.z, w1.w};
#pragma unroll
            for (int i = 0; i < 8; i++) {
                acc[i][0] += wv[i] * rx.x;
                acc[i][1] += wv[i] * rx.y;
                acc[i][2] += wv[i] * rx.z;
                acc[i][3] += wv[i] * rx.w;
            }
        }
        __syncthreads();
    }

    const int nn0 = n0 + tx * 4;
    if (nn0 >= Nlen) return;
#pragma unroll
    for (int i = 0; i < 8; i++) {
        int o = om0 + ty * 8 + i;
        if (o >= Cout) continue;
        float bi = bias  ? bias[o]  : 0.f;
        float sc = scale ? scale[o] : 1.f;
        float sh = shift ? shift[o] : 0.f;
        float4 yv;
        yv.x = (acc[i][0] + bi) * sc + sh;
        yv.y = (acc[i][1] + bi) * sc + sh;
        yv.z = (acc[i][2] + bi) * sc + sh;
        yv.w = (acc[i][3] + bi) * sc + sh;
        if (do_relu) {
            yv.x = fmaxf(yv.x, 0.f); yv.y = fmaxf(yv.y, 0.f);
            yv.z = fmaxf(yv.z, 0.f); yv.w = fmaxf(yv.w, 0.f);
        }
        if (round_out) {
            yv.x = tfb(yv.x); yv.y = tfb(yv.y);
            yv.z = tfb(yv.z); yv.w = tfb(yv.w);
        }
        size_t off = ((size_t)b * Cout + o) * Nlen + nn0;
        if (Ypre) *(float4*)&Ypre[off] = yv;
        if (resid) {
            float4 rv = *(const float4*)&resid[off];
            yv.x += rv.x; yv.y += rv.y; yv.z += rv.z; yv.w += rv.w;
        }
        *(float4*)&Y[off] = yv;
    }
}

// ---------------- flash attention (tf32 mma, online softmax, split-KV) ----------------
#define FBQ 128
#define FBK 64
#define KSS 72
#define VSS 80
#define PSS 80

__global__ void __launch_bounds__(256, 3)
flash_attn_mma(const float* __restrict__ Q, const float* __restrict__ K,
               const float* __restrict__ V, const float* __restrict__ maskLogits,
               float* __restrict__ O,
               float* __restrict__ Opart, float* __restrict__ Mpart, float* __restrict__ Lpart,
               int Nq, int Nk, int nsplit, int kvchunk)
{
    __shared__ float ks[DHH][KSS];
    __shared__ float vB[DHH][VSS];
    __shared__ __align__(16) float ps[8][16][PSS];
    __shared__ float ms[FBK];

    const int bh = blockIdx.y;
    const int b  = bh / HH;
    const int h  = bh % HH;
    const int q0 = blockIdx.x * FBQ;
    const int sp = blockIdx.z;
    const int tid = threadIdx.x;
    const int w = tid >> 5, lane = tid & 31;
    const int g = lane >> 2, t4 = lane & 3;
    const float sm_scale = 0.17677669529663687f;  // 1/sqrt(32)
    const float MASKV = -1.0e6f * 0.17677669529663687f;

    const float* Qb = Q + ((size_t)b * CC + h * DHH) * Nq;
    const float* Kb = K + ((size_t)b * CC + h * DHH) * Nk;
    const float* Vb = V + ((size_t)b * CC + h * DHH) * Nk;

    float* qbuf = &ps[0][0][0];
    for (int i = tid; i < DHH * (FBQ / 4); i += 256) {
        int d  = i / (FBQ / 4);
        int r4 = (i % (FBQ / 4)) * 4;
        int nn = q0 + r4;
        float4 qv = make_float4(0.f, 0.f, 0.f, 0.f);
        if (nn + 3 < Nq) qv = *(const float4*)&Qb[(size_t)d * Nq + nn];
        else {
            if (nn + 0 < Nq) qv.x = Qb[(size_t)d * Nq + nn + 0];
            if (nn + 1 < Nq) qv.y = Qb[(size_t)d * Nq + nn + 1];
            if (nn + 2 < Nq) qv.z = Qb[(size_t)d * Nq + nn + 2];
        }
        *(float4*)&qbuf[d * FBQ + r4] = qv;
    }
    __syncthreads();

    uint32_t aq[4][4];
    const int qr = w * 16;
#pragma unroll
    for (int s = 0; s < 4; s++) {
        aq[s][0] = __float_as_uint(qbuf[(s * 8 + t4) * FBQ + qr + g]);
        aq[s][1] = __float_as_uint(qbuf[(s * 8 + t4) * FBQ + qr + g + 8]);
        aq[s][2] = __float_as_uint(qbuf[(s * 8 + t4 + 4) * FBQ + qr + g]);
        aq[s][3] = __float_as_uint(qbuf[(s * 8 + t4 + 4) * FBQ + qr + g + 8]);
    }

    float o[4][4];
#pragma unroll
    for (int nt = 0; nt < 4; nt++) { o[nt][0] = o[nt][1] = o[nt][2] = o[nt][3] = 0.f; }
    float m_lo = -3.0e38f, m_hi = -3.0e38f, l_lo = 0.f, l_hi = 0.f;

    const int kvbeg = sp * kvchunk;
    const int kvend = min(Nk, kvbeg + kvchunk);

    for (int k0 = kvbeg; k0 < kvend; k0 += FBK) {
        if (tid < FBK) {
            int nn = k0 + tid;
            float f;
            if (nn >= Nk)          f = 2.f;
            else if (maskLogits)   f = (maskLogits[(size_t)b * Nk + nn] > 0.f) ? 0.f : 1.f;
            else                   f = 0.f;
            ms[tid] = f;
        }
        for (int i = tid; i < DHH * (FBK / 4); i += 256) {
            int d  = i / (FBK / 4);
            int c4 = (i % (FBK / 4)) * 4;
            int nn = k0 + c4;
            float4 kv = make_float4(0.f, 0.f, 0.f, 0.f);
            float4 vv = make_float4(0.f, 0.f, 0.f, 0.f);
            if (nn < Nk) {
                kv = *(const float4*)&Kb[(size_t)d * Nk + nn];
                vv = *(const float4*)&Vb[(size_t)d * Nk + nn];
            }
            *(float4*)&ks[d][c4] = kv;
            *(float4*)&vB[d][c4] = vv;
        }
        __syncthreads();

        float sv[8][4];
#pragma unroll
        for (int nt = 0; nt < 8; nt++) {
            sv[nt][0] = sv[nt][1] = sv[nt][2] = sv[nt][3] = 0.f;
#pragma unroll
            for (int s = 0; s < 4; s++) {
                uint32_t bf[2];
                bf[0] = __float_as_uint(ks[s * 8 + t4][nt * 8 + g]);
                bf[1] = __float_as_uint(ks[s * 8 + t4 + 4][nt * 8 + g]);
                mma8(sv[nt], aq[s], bf);
            }
        }

        float tmax_lo = -3.0e38f, tmax_hi = -3.0e38f;
#pragma unroll
        for (int nt = 0; nt < 8; nt++) {
            float m0 = ms[nt * 8 + 2 * t4];
            float m1 = ms[nt * 8 + 2 * t4 + 1];
            sv[nt][0] = (m0 == 0.f) ? sv[nt][0] * sm_scale : ((m0 == 1.f) ? MASKV : -3.0e38f);
            sv[nt][1] = (m1 == 0.f) ? sv[nt][1] * sm_scale : ((m1 == 1.f) ? MASKV : -3.0e38f);
            sv[nt][2] = (m0 == 0.f) ? sv[nt][2] * sm_scale : ((m0 == 1.f) ? MASKV : -3.0e38f);
            sv[nt][3] = (m1 == 0.f) ? sv[nt][3] * sm_scale : ((m1 == 1.f) ? MASKV : -3.0e38f);
            tmax_lo = fmaxf(tmax_lo, fmaxf(sv[nt][0], sv[nt][1]));
            tmax_hi = fmaxf(tmax_hi, fmaxf(sv[nt][2], sv[nt][3]));
        }
        tmax_lo = fmaxf(tmax_lo, __shfl_xor_sync(0xffffffffu, tmax_lo, 1));
        tmax_lo = fmaxf(tmax_lo, __shfl_xor_sync(0xffffffffu, tmax_lo, 2));
        tmax_hi = fmaxf(tmax_hi, __shfl_xor_sync(0xffffffffu, tmax_hi, 1));
        tmax_hi = fmaxf(tmax_hi, __shfl_xor_sync(0xffffffffu, tmax_hi, 2));

        float mn_lo = fmaxf(m_lo, tmax_lo);
        float mn_hi = fmaxf(m_hi, tmax_hi);
        float corr_lo = __expf(m_lo - mn_lo);
        float corr_hi = __expf(m_hi - mn_hi);
        m_lo = mn_lo; m_hi = mn_hi;

        float rs_lo = 0.f, rs_hi = 0.f;
#pragma unroll
        for (int nt = 0; nt < 8; nt++) {
            float p0 = __expf(sv[nt][0] - mn_lo);
            float p1 = __expf(sv[nt][1] - mn_lo);
            float p2 = __expf(sv[nt][2] - mn_hi);
            float p3 = __expf(sv[nt][3] - mn_hi);
            rs_lo += p0 + p1;
            rs_hi += p2 + p3;
            *(float2*)&ps[w][g][nt * 8 + 2 * t4]     = make_float2(tfb(p0), tfb(p1));
            *(float2*)&ps[w][g + 8][nt * 8 + 2 * t4] = make_float2(tfb(p2), tfb(p3));
        }
        rs_lo += __shfl_xor_sync(0xffffffffu, rs_lo, 1);
        rs_lo += __shfl_xor_sync(0xffffffffu, rs_lo, 2);
        rs_hi += __shfl_xor_sync(0xffffffffu, rs_hi, 1);
        rs_hi += __shfl_xor_sync(0xffffffffu, rs_hi, 2);
        l_lo = l_lo * corr_lo + rs_lo;
        l_hi = l_hi * corr_hi + rs_hi;
#pragma unroll
        for (int nt = 0; nt < 4; nt++) {
            o[nt][0] *= corr_lo; o[nt][1] *= corr_lo;
            o[nt][2] *= corr_hi; o[nt][3] *= corr_hi;
        }
        __syncwarp();

        float4 plo[4], phi[4];
#pragma unroll
        for (int j = 0; j < 4; j++) {
            plo[j] = *(const float4*)&ps[w][g][(t4 + 4 * j) * 4];
            phi[j] = *(const float4*)&ps[w][g + 8][(t4 + 4 * j) * 4];
        }
        uint32_t ap[8][4];
#pragma unroll
        for (int s = 0; s < 8; s++) {
            int j = s >> 1, e = (s & 1) * 2;
            const float* pl = (const float*)&plo[j];
            const float* ph = (const float*)&phi[j];
            ap[s][0] = __float_as_uint(pl[e]);
            ap[s][1] = __float_as_uint(ph[e]);
            ap[s][2] = __float_as_uint(pl[e + 1]);
            ap[s][3] = __float_as_uint(ph[e + 1]);
        }
#pragma unroll
        for (int nt = 0; nt < 4; nt++) {
            float4 fv[4];
#pragma unroll
            for (int j = 0; j < 4; j++)
                fv[j] = *(const float4*)&vB[nt * 8 + g][(t4 + 4 * j) * 4];
#pragma unroll
            for (int s = 0; s < 8; s++) {
                int j = s >> 1, e = (s & 1) * 2;
                const float* vv = (const float*)&fv[j];
                uint32_t bf[2];
                bf[0] = __float_as_uint(vv[e]);
                bf[1] = __float_as_uint(vv[e + 1]);
                mma8(o[nt], ap[s], bf);
            }
        }
        __syncthreads();
    }

    const int r_lo = q0 + w * 16 + g;
    const int r_hi = r_lo + 8;
    if (nsplit == 1) {
        float* Ob = O + ((size_t)b * CC + h * DHH) * Nq;
        float il_lo = 1.f / l_lo, il_hi = 1.f / l_hi;
#pragma unroll
        for (int nt = 0; nt < 4; nt++) {
            int d0 = nt * 8 + 2 * t4;
            if (r_lo < Nq) {
                Ob[(size_t)d0 * Nq + r_lo]       = o[nt][0] * il_lo;
                Ob[(size_t)(d0 + 1) * Nq + r_lo] = o[nt][1] * il_lo;
            }
            if (r_hi < Nq) {
                Ob[(size_t)d0 * Nq + r_hi]       = o[nt][2] * il_hi;
                Ob[(size_t)(d0 + 1) * Nq + r_hi] = o[nt][3] * il_hi;
            }
        }
    } else {
        float* Op = Opart + ((size_t)sp * BH + bh) * DHH * Nq;
#pragma unroll
        for (int nt = 0; nt < 4; nt++) {
            int d0 = nt * 8 + 2 * t4;
            if (r_lo < Nq) {
                Op[(size_t)d0 * Nq + r_lo]       = o[nt][0];
                Op[(size_t)(d0 + 1) * Nq + r_lo] = o[nt][1];
            }
            if (r_hi < Nq) {
                Op[(size_t)d0 * Nq + r_hi]       = o[nt][2];
                Op[(size_t)(d0 + 1) * Nq + r_hi] = o[nt][3];
            }
        }
        if (t4 == 0) {
            size_t base = ((size_t)sp * BH + bh) * Nq;
            if (r_lo < Nq) { Mpart[base + r_lo] = m_lo; Lpart[base + r_lo] = l_lo; }
            if (r_hi < Nq) { Mpart[base + r_hi] = m_hi; Lpart[base + r_hi] = l_hi; }
        }
    }
}

__global__ void flash_combine(const float* __restrict__ Opart, const float* __restrict__ Mpart,
                              const float* __restrict__ Lpart, float* __restrict__ O,
                              int Nq, int nsplit)
{
    int idx = blockIdx.x * blockDim.x + threadIdx.x;
    if (idx >= BH * Nq) return;
    int n  = idx % Nq;
    int bh = idx / Nq;
    int b  = bh / HH;
    int h  = bh % HH;

    float M = -3.0e38f;
    for (int s = 0; s < nsplit; s++)
        M = fmaxf(M, Mpart[((size_t)s * BH + bh) * Nq + n]);
    float w[NSPLIT];
    float L = 0.f;
    for (int s = 0; s < nsplit; s++) {
        float ws = __expf(Mpart[((size_t)s * BH + bh) * Nq + n] - M);
        w[s] = ws;
        L += ws * Lpart[((size_t)s * BH + bh) * Nq + n];
    }
    float inv = 1.f / L;
    float* Ob = O + ((size_t)b * CC + h * DHH) * Nq + n;
    for (int d = 0; d < DHH; d++) {
        float acc = 0.f;
        for (int s = 0; s < nsplit; s++)
            acc += w[s] * Opart[(((size_t)s * BH + bh) * DHH + d) * Nq + n];
        Ob[(size_t)d * Nq] = acc * inv;
    }
}

// ---------------- small conv (Cout small: 16/4/1) ----------------
__global__ void conv_small(const float* __restrict__ W, const float* __restrict__ bias,
                           const float* __restrict__ X, float* __restrict__ Y,
                           int Cout, int Cin, int Nlen)
{
    int idx = blockIdx.x * blockDim.x + threadIdx.x;
    int total = BB * Cout * Nlen;
    if (idx >= total) return;
    int n = idx % Nlen;
    int o = (idx / Nlen) % Cout;
    int b = idx / (Nlen * Cout);
    float acc = bias[o];
    const float* Xb = X + (size_t)b * Cin * Nlen + n;
    const float* Wo = W + (size_t)o * Cin;
    for (int c = 0; c < Cin; c++) acc += Wo[c] * Xb[(size_t)c * Nlen];
    Y[idx] = acc;
}

// ---------------- instance norm + scale/shift + relu, in place ----------------
__global__ void instnorm_relu(float* __restrict__ X, const float* __restrict__ s,
                              const float* __restrict__ sh, int Cc, int Nlen)
{
    int bc = blockIdx.x;
    int c  = bc % Cc;
    float* x = X + (size_t)bc * Nlen;
    int tid = threadIdx.x;

    float sum = 0.f, sq = 0.f;
    for (int i = tid; i < Nlen; i += blockDim.x) { float v = x[i]; sum += v; sq += v * v; }
#pragma unroll
    for (int off = 16; off >= 1; off >>= 1) {
        sum += __shfl_xor_sync(0xffffffffu, sum, off);
        sq  += __shfl_xor_sync(0xffffffffu, sq,  off);
    }
    __shared__ float ssum[8], ssq[8];
    __shared__ float smu, sinv;
    int w = tid >> 5;
    if ((tid & 31) == 0) { ssum[w] = sum; ssq[w] = sq; }
    __syncthreads();
    if (tid == 0) {
        float S = 0.f, Q2 = 0.f;
        for (int i = 0; i < (int)(blockDim.x >> 5); i++) { S += ssum[i]; Q2 += ssq[i]; }
        float mu  = S / Nlen;
        float var = fmaxf(Q2 / Nlen - mu * mu, 0.f);
        smu  = mu;
        sinv = rsqrtf(var + 1e-3f);
    }
    __syncthreads();
    float scv = s[c] * sinv, mu = smu, shv = sh[c];
    for (int i = tid; i < Nlen; i += blockDim.x) {
        float v = (x[i] - mu) * scv + shv;
        x[i] = fmaxf(v, 0.f);
    }
}

// ---------------- host ----------------
static void run_conv(const float* WT, const float* bias,
                     const float* X1, const float* X2, int split,
                     float* Y, float* Ypre, int Cout, int Cin, int Nlen,
                     const float* scale, const float* shift, int relu,
                     const float* resid, int round_out)
{
    dim3 grid((Nlen + 63) / 64, Cout / 64, BB);
    conv_gemm<<<grid, 128>>>(WT, bias, X1, X2, split, Y, Ypre, Cout, Cin, Nlen,
                             scale, shift, relu, resid, round_out);
}

extern "C" void kernel_launch(void* const* d_in, const int* in_sizes, int n_in,
                              void* d_out, int out_size)
{
    const float* d_in1      = (const float*)d_in[1];
    const float* feat_piece = (const float*)d_in[2];
    const float* logits_in  = (const float*)d_in[3];
    const float* Wq  = (const float*)d_in[4];
    const float* bq  = (const float*)d_in[5];
    const float* Wk  = (const float*)d_in[6];
    const float* bk  = (const float*)d_in[7];
    const float* Wv  = (const float*)d_in[8];
    const float* bv  = (const float*)d_in[9];
    const float* Wm  = (const float*)d_in[10];
    const float* bm  = (const float*)d_in[11];
    const float* Wc1 = (const float*)d_in[12];
    const float* bc1 = (const float*)d_in[13];
    const float* bns = (const float*)d_in[14];
    const float* bnsh= (const float*)d_in[15];
    const float* Wc2 = (const float*)d_in[16];
    const float* bc2 = (const float*)d_in[17];
    const float* iW1 = (const float*)d_in[18];
    const float* ib1 = (const float*)d_in[19];
    const float* ibn1s  = (const float*)d_in[20];
    const float* ibn1sh = (const float*)d_in[21];
    const float* iW2 = (const float*)d_in[22];
    const float* ib2 = (const float*)d_in[23];
    const float* ibn2s  = (const float*)d_in[24];
    const float* ibn2sh = (const float*)d_in[25];
    const float* iW3 = (const float*)d_in[26];
    const float* ib3 = (const float*)d_in[27];
    const float* ibn3s  = (const float*)d_in[28];
    const float* ibn3sh = (const float*)d_in[29];
    const float* iW4 = (const float*)d_in[30];
    const float* ib4 = (const float*)d_in[31];

    float *Q, *K, *V, *AO, *Hb, *F1, *F2, *XH, *T1, *T2, *T3, *OP, *MP, *LP, *WF, *BF, *WT;
    cudaGetSymbolAddress((void**)&Q,   g_Q);
    cudaGetSymbolAddress((void**)&K,   g_K);
    cudaGetSymbolAddress((void**)&V,   g_V);
    cudaGetSymbolAddress((void**)&AO,  g_AO);
    cudaGetSymbolAddress((void**)&Hb,  g_Hb);
    cudaGetSymbolAddress((void**)&F1,  g_F1);
    cudaGetSymbolAddress((void**)&F2,  g_F2);
    cudaGetSymbolAddress((void**)&XH,  g_XH);
    cudaGetSymbolAddress((void**)&T1,  g_T1);
    cudaGetSymbolAddress((void**)&T2,  g_T2);
    cudaGetSymbolAddress((void**)&T3,  g_T3);
    cudaGetSymbolAddress((void**)&OP,  g_OP);
    cudaGetSymbolAddress((void**)&MP,  g_MP);
    cudaGetSymbolAddress((void**)&LP,  g_LP);
    cudaGetSymbolAddress((void**)&WF,  g_WF);
    cudaGetSymbolAddress((void**)&BF,  g_BF);
    cudaGetSymbolAddress((void**)&WT,  g_WT);

    // weight prep (runs every launch; deterministic)
    transpose_all<<<(WT_TOT + 255) / 256, 256>>>(Wq, Wk, Wv, Wc2, iW1, WT);
    fuse_wc1<<<(3 * 256 * 256 + 255) / 256, 256>>>(Wc1, Wm, WF);
    fuse_bc1<<<(3 * 256 + 255) / 256, 256>>>(Wc1, bc1, bm, BF);

    auto attn = [&](const float* x1, const float* x2, const float* mask,
                    int Nq, int Nk, int li, float* out, float* outPre, const float* resid) {
        const int C2 = 2 * CC;
        run_conv(WT + WT_Q + (size_t)li * CC * CC, bq + (size_t)li * CC, x1, nullptr, CC,
                 Q, nullptr, CC, CC, Nq, nullptr, nullptr, 0, nullptr, 1);
        run_conv(WT + WT_K + (size_t)li * CC * CC, bk + (size_t)li * CC, x2, nullptr, CC,
                 K, nullptr, CC, CC, Nk, nullptr, nullptr, 0, nullptr, 1);
        run_conv(WT + WT_V + (size_t)li * CC * CC, bv + (size_t)li * CC, x2, nullptr, CC,
                 V, nullptr, CC, CC, Nk, nullptr, nullptr, 0, nullptr, 1);

        int qblocks = (Nq + FBQ - 1) / FBQ;
        int nsplit  = 1;
        if (qblocks * BH < 300) nsplit = NSPLIT;
        int nkt = (Nk + FBK - 1) / FBK;
        int kvchunk = ((nkt + nsplit - 1) / nsplit) * FBK;

        dim3 fg(qblocks, BH, nsplit);
        flash_attn_mma<<<fg, 256>>>(Q, K, V, mask, AO, OP, MP, LP, Nq, Nk, nsplit, kvchunk);
        if (nsplit > 1) {
            int tot = BH * Nq;
            flash_combine<<<(tot + 255) / 256, 256>>>(OP, MP, LP, AO, Nq, nsplit);
        }

        run_conv(WF + (size_t)li * C2 * C2, BF + (size_t)li * C2, x1, AO, CC,
                 Hb, nullptr, C2, C2, Nq, bns + (size_t)li * C2, bnsh + (size_t)li * C2, 1, nullptr, 0);
        run_conv(WT + WT_C2 + (size_t)li * CC * C2, bc2 + (size_t)li * CC, Hb, nullptr, C2,
                 out, outPre, CC, C2, Nq, nullptr, nullptr, 0, resid, 0);
    };

    float* dnew   = (float*)d_out;                 // [B,C,N]
    float* logout = dnew + (size_t)BB * CC * NN;   // [B,N]

    attn(feat_piece, d_in1, logits_in, MM, NN, 0, F1, nullptr, feat_piece);
    attn(F1, F1, nullptr, MM, MM, 1, F2, nullptr, F1);
    attn(d_in1, F2, nullptr, NN, MM, 2, dnew, XH, d_in1);

    // head on x = d_new - d_old == XH
    run_conv(WT + WT_I1, ib1, XH, nullptr, CC, T1, nullptr, 64, CC, NN, nullptr, nullptr, 0, nullptr, 0);
    instnorm_relu<<<BB * 64, 256>>>(T1, ibn1s, ibn1sh, 64, NN);

    conv_small<<<(BB * 16 * NN + 255) / 256, 256>>>(iW2, ib2, T1, T2, 16, 64, NN);
    instnorm_relu<<<BB * 16, 256>>>(T2, ibn2s, ibn2sh, 16, NN);

    conv_small<<<(BB * 4 * NN + 255) / 256, 256>>>(iW3, ib3, T2, T3, 4, 16, NN);
    instnorm_relu<<<BB * 4, 256>>>(T3, ibn3s, ibn3sh, 4, NN);

    conv_small<<<(BB * 1 * NN + 255) / 256, 256>>>(iW4, ib4, T3, logout, 1, 4, NN);
}

// round 13
// speedup vs baseline: 1.5751x; 1.5751x over previous
#include <cuda_runtime.h>
#include <math.h>
#include <stdint.h>

// Problem constants
#define BB 2
#define CC 128
#define NN 6000
#define MM 1500
#define HH 4
#define DHH 32
#define BH (BB*HH)
#define NSPLIT 4

// ---------------- scratch (static device globals; no allocation) ----------------
__device__ float g_Q  [BB*CC*NN];
__device__ float g_K  [BB*CC*NN];
__device__ float g_V  [BB*CC*NN];
__device__ float g_AO [BB*CC*NN];
__device__ float g_Hb [BB*2*CC*NN];
__device__ float g_F1 [BB*CC*MM];
__device__ float g_F2 [BB*CC*MM];
__device__ float g_XH [BB*CC*NN];
__device__ float g_T1 [BB*64*NN];
__device__ float g_T2 [BB*16*NN];
__device__ float g_T3 [BB*4*NN];
// split-KV partials
__device__ float g_OP [NSPLIT*BH*DHH*NN];
__device__ float g_MP [NSPLIT*BH*NN];
__device__ float g_LP [NSPLIT*BH*NN];
// fused Wc1' (K-major): WF[l][c][o]
__device__ float g_WF [3*2*CC*2*CC];
__device__ float g_BF [3*2*CC];
// transposed weights (K-major): Wq(3),Wk(3),Wv(3) 128x128; Wc2(3) 256x128; iW1 128x64
#define WT_Q   0
#define WT_K   49152
#define WT_V   98304
#define WT_C2  147456
#define WT_I1  245760
#define WT_TOT 253952
__device__ float g_WT [WT_TOT];

// ---------------- tf32 helpers ----------------
__device__ __forceinline__ uint32_t f2tf(float f) {
    uint32_t u;
    asm("cvt.rna.tf32.f32 %0, %1;" : "=r"(u) : "f"(f));
    return u;
}
__device__ __forceinline__ float tfb(float f) { return __uint_as_float(f2tf(f)); }

__device__ __forceinline__ void mma8(float* d, const uint32_t* a, const uint32_t* b) {
    asm volatile("mma.sync.aligned.m16n8k8.row.col.f32.tf32.tf32.f32 "
                 "{%0,%1,%2,%3}, {%4,%5,%6,%7}, {%8,%9}, {%0,%1,%2,%3};\n"
                 : "+f"(d[0]), "+f"(d[1]), "+f"(d[2]), "+f"(d[3])
                 : "r"(a[0]), "r"(a[1]), "r"(a[2]), "r"(a[3]),
                   "r"(b[0]), "r"(b[1]));
}

__device__ __forceinline__ uint32_t smem_u32(const void* p) {
    uint32_t a;
    asm("{ .reg .u64 t; cvta.to.shared.u64 t, %1; cvt.u32.u64 %0, t; }" : "=r"(a) : "l"(p));
    return a;
}
__device__ __forceinline__ void cp16(uint32_t dst, const void* src, uint32_t ssz) {
    asm volatile("cp.async.ca.shared.global [%0], [%1], 16, %2;"
                 :: "r"(dst), "l"(src), "r"(ssz));
}

// ---------------- weight prep kernels ----------------
__global__ void transpose_all(const float* __restrict__ Wq, const float* __restrict__ Wk,
                              const float* __restrict__ Wv, const float* __restrict__ Wc2,
                              const float* __restrict__ iW1, float* __restrict__ WT)
{
    int idx = blockIdx.x * blockDim.x + threadIdx.x;
    if (idx >= WT_TOT) return;
    float v;
    if (idx < WT_C2) {
        int seg = idx / 49152;
        int r   = idx % 49152;
        int l   = r / 16384;
        int e   = r % 16384;
        int c   = e >> 7, o = e & 127;
        const float* Wsrc = (seg == 0) ? Wq : ((seg == 1) ? Wk : Wv);
        v = Wsrc[l * 16384 + o * 128 + c];
    } else if (idx < WT_I1) {
        int r = idx - WT_C2;
        int l = r / 32768;
        int e = r % 32768;
        int c = e >> 7, o = e & 127;
        v = Wc2[l * 32768 + o * 256 + c];
    } else {
        int e = idx - WT_I1;
        int c = e >> 6, o = e & 63;
        v = iW1[o * 128 + c];
    }
    WT[idx] = v;
}

__global__ void fuse_wc1(const float* __restrict__ Wc1, const float* __restrict__ Wm,
                         float* __restrict__ WF)
{
    int idx = blockIdx.x * blockDim.x + threadIdx.x;
    if (idx >= 3 * 256 * 256) return;
    int c = idx & 255;
    int o = (idx >> 8) & 255;
    int l = idx >> 16;
    const float* Wc1l = Wc1 + (size_t)l * 256 * 256;
    float v;
    if (c < CC) {
        v = Wc1l[o * 256 + c];
    } else {
        const float* wrow = Wc1l + o * 256 + CC;
        const float* wm   = Wm + (size_t)l * CC * CC;
        int cc = c - CC;
        float acc = 0.f;
#pragma unroll 4
        for (int k = 0; k < CC; k++) acc += wrow[k] * wm[k * CC + cc];
        v = acc;
    }
    WF[(size_t)l * 65536 + c * 256 + o] = v;
}

__global__ void fuse_bc1(const float* __restrict__ Wc1, const float* __restrict__ bc1,
                         const float* __restrict__ bm, float* __restrict__ BF)
{
    int idx = blockIdx.x * blockDim.x + threadIdx.x;
    if (idx >= 3 * 256) return;
    int o = idx & 255, l = idx >> 8;
    const float* wrow = Wc1 + (size_t)l * 256 * 256 + o * 256 + CC;
    const float* bml  = bm + l * CC;
    float acc = bc1[l * 256 + o];
#pragma unroll 4
    for (int k = 0; k < CC; k++) acc += wrow[k] * bml[k];
    BF[idx] = acc;
}

// ---------------- fp32 GEMM for 1x1 conv: cp.async double-buffered (64-out tile) ----------------
#define CBK 32

__global__ void __launch_bounds__(128)
conv_gemm(const float* __restrict__ WT, const float* __restrict__ bias,
          const float* __restrict__ X1, const float* __restrict__ X2, int split,
          float* __restrict__ Y, float* __restrict__ Ypre,
          int Cout, int Cin, int Nlen,
          const float* __restrict__ scale, const float* __restrict__ shift,
          int do_relu, const float* __restrict__ resid, int round_out)
{
    __shared__ __align__(16) float Ws[2][CBK][64];
    __shared__ __align__(16) float Xs[2][CBK][64];

    const int b   = blockIdx.z;
    const int om0 = blockIdx.y * 64;
    const int n0  = blockIdx.x * 64;
    const int tid = threadIdx.x;
    const int tx  = tid & 15;
    const int ty  = tid >> 4;

    float acc[8][4];
#pragma unroll
    for (int i = 0; i < 8; i++)
#pragma unroll
        for (int j = 0; j < 4; j++) acc[i][j] = 0.f;

    const int Ci2 = Cin - split;

    auto stage = [&](int k0, int buf) {
#pragma unroll
        for (int i = tid; i < 32 * 16; i += 128) {
            int kk = i >> 4, o4 = (i & 15) * 4;
            cp16(smem_u32(&Ws[buf][kk][o4]), &WT[(size_t)(k0 + kk) * Cout + om0 + o4], 16);
        }
#pragma unroll
        for (int i = tid; i < 32 * 16; i += 128) {
            int kk = i >> 4, n4 = (i & 15) * 4;
            int c = k0 + kk;
            int n = n0 + n4;
            int nc = (n < Nlen) ? n : 0;
            const float* src;
            if (c < split) src = &X1[((size_t)b * split + c) * Nlen + nc];
            else           src = &X2[((size_t)b * Ci2 + (c - split)) * Nlen + nc];
            cp16(smem_u32(&Xs[buf][kk][n4]), src, (n < Nlen) ? 16u : 0u);
        }
    };

    const int nch = Cin / CBK;
    stage(0, 0);
    asm volatile("cp.async.commit_group;");

    for (int ch = 0; ch < nch; ch++) {
        if (ch + 1 < nch) {
            stage((ch + 1) * CBK, (ch + 1) & 1);
            asm volatile("cp.async.commit_group;");
            asm volatile("cp.async.wait_group 1;");
        } else {
            asm volatile("cp.async.wait_group 0;");
        }
        __syncthreads();

        const float (*Wb)[64] = Ws[ch & 1];
        const float (*Xb)[64] = Xs[ch & 1];
#pragma unroll 8
        for (int kk = 0; kk < CBK; kk++) {
            float4 w0 = *(const float4*)&Wb[kk][ty * 8];
            float4 w1 = *(const float4*)&Wb[kk][ty * 8 + 4];
            float4 rx = *(const float4*)&Xb[kk][tx * 4];
            const float wv[8] = {w0.x, w0.y, w0.z, w0.w, w1.x, w1.y, w1.z, w1.w};
#pragma unroll
            for (int i = 0; i < 8; i++) {
                acc[i][0] += wv[i] * rx.x;
                acc[i][1] += wv[i] * rx.y;
                acc[i][2] += wv[i] * rx.z;
                acc[i][3] += wv[i] * rx.w;
            }
        }
        __syncthreads();
    }

    const int nn0 = n0 + tx * 4;
    if (nn0 >= Nlen) return;
#pragma unroll
    for (int i = 0; i < 8; i++) {
        int o = om0 + ty * 8 + i;
        if (o >= Cout) continue;
        float bi = bias  ? bias[o]  : 0.f;
        float sc = scale ? scale[o] : 1.f;
        float sh = shift ? shift[o] : 0.f;
        float4 yv;
        yv.x = (acc[i][0] + bi) * sc + sh;
        yv.y = (acc[i][1] + bi) * sc + sh;
        yv.z = (acc[i][2] + bi) * sc + sh;
        yv.w = (acc[i][3] + bi) * sc + sh;
        if (do_relu) {
            yv.x = fmaxf(yv.x, 0.f); yv.y = fmaxf(yv.y, 0.f);
            yv.z = fmaxf(yv.z, 0.f); yv.w = fmaxf(yv.w, 0.f);
        }
        if (round_out) {
            yv.x = tfb(yv.x); yv.y = tfb(yv.y);
            yv.z = tfb(yv.z); yv.w = tfb(yv.w);
        }
        size_t off = ((size_t)b * Cout + o) * Nlen + nn0;
        if (Ypre) *(float4*)&Ypre[off] = yv;
        if (resid) {
            float4 rv = *(const float4*)&resid[off];
            yv.x += rv.x; yv.y += rv.y; yv.z += rv.z; yv.w += rv.w;
        }
        *(float4*)&Y[off] = yv;
    }
}

// ---------------- 32-out-tile variant: doubles CTA count for starved launches ----------------
__global__ void __launch_bounds__(128)
conv_gemm32(const float* __restrict__ WT, const float* __restrict__ bias,
            const float* __restrict__ X1, const float* __restrict__ X2, int split,
            float* __restrict__ Y, float* __restrict__ Ypre,
            int Cout, int Cin, int Nlen,
            const float* __restrict__ scale, const float* __restrict__ shift,
            int do_relu, const float* __restrict__ resid, int round_out)
{
    __shared__ __align__(16) float Ws[2][CBK][32];
    __shared__ __align__(16) float Xs[2][CBK][64];

    const int b   = blockIdx.z;
    const int om0 = blockIdx.y * 32;
    const int n0  = blockIdx.x * 64;
    const int tid = threadIdx.x;
    const int tx  = tid & 15;
    const int ty  = tid >> 4;

    float acc[4][4];
#pragma unroll
    for (int i = 0; i < 4; i++)
#pragma unroll
        for (int j = 0; j < 4; j++) acc[i][j] = 0.f;

    const int Ci2 = Cin - split;

    auto stage = [&](int k0, int buf) {
        // W: 32 k-rows x 8 float4 along o
#pragma unroll
        for (int i = tid; i < 32 * 8; i += 128) {
            int kk = i >> 3, o4 = (i & 7) * 4;
            cp16(smem_u32(&Ws[buf][kk][o4]), &WT[(size_t)(k0 + kk) * Cout + om0 + o4], 16);
        }
        // X: 32 k-rows x 16 float4 along n
#pragma unroll
        for (int i = tid; i < 32 * 16; i += 128) {
            int kk = i >> 4, n4 = (i & 15) * 4;
            int c = k0 + kk;
            int n = n0 + n4;
            int nc = (n < Nlen) ? n : 0;
            const float* src;
            if (c < split) src = &X1[((size_t)b * split + c) * Nlen + nc];
            else           src = &X2[((size_t)b * Ci2 + (c - split)) * Nlen + nc];
            cp16(smem_u32(&Xs[buf][kk][n4]), src, (n < Nlen) ? 16u : 0u);
        }
    };

    const int nch = Cin / CBK;
    stage(0, 0);
    asm volatile("cp.async.commit_group;");

    for (int ch = 0; ch < nch; ch++) {
        if (ch + 1 < nch) {
            stage((ch + 1) * CBK, (ch + 1) & 1);
            asm volatile("cp.async.commit_group;");
            asm volatile("cp.async.wait_group 1;");
        } else {
            asm volatile("cp.async.wait_group 0;");
        }
        __syncthreads();

        const float (*Wb)[32] = Ws[ch & 1];
        const float (*Xb)[64] = Xs[ch & 1];
#pragma unroll 8
        for (int kk = 0; kk < CBK; kk++) {
            float4 w0 = *(const float4*)&Wb[kk][ty * 4];
            float4 rx = *(const float4*)&Xb[kk][tx * 4];
            acc[0][0] += w0.x * rx.x; acc[0][1] += w0.x * rx.y; acc[0][2] += w0.x * rx.z; acc[0][3] += w0.x * rx.w;
            acc[1][0] += w0.y * rx.x; acc[1][1] += w0.y * rx.y; acc[1][2] += w0.y * rx.z; acc[1][3] += w0.y * rx.w;
            acc[2][0] += w0.z * rx.x; acc[2][1] += w0.z * rx.y; acc[2][2] += w0.z * rx.z; acc[2][3] += w0.z * rx.w;
            acc[3][0] += w0.w * rx.x; acc[3][1] += w0.w * rx.y; acc[3][2] += w0.w * rx.z; acc[3][3] += w0.w * rx.w;
        }
        __syncthreads();
    }

    const int nn0 = n0 + tx * 4;
    if (nn0 >= Nlen) return;
#pragma unroll
    for (int i = 0; i < 4; i++) {
        int o = om0 + ty * 4 + i;
        if (o >= Cout) continue;
        float bi = bias  ? bias[o]  : 0.f;
        float sc = scale ? scale[o] : 1.f;
        float sh = shift ? shift[o] : 0.f;
        float4 yv;
        yv.x = (acc[i][0] + bi) * sc + sh;
        yv.y = (acc[i][1] + bi) * sc + sh;
        yv.z = (acc[i][2] + bi) * sc + sh;
        yv.w = (acc[i][3] + bi) * sc + sh;
        if (do_relu) {
            yv.x = fmaxf(yv.x, 0.f); yv.y = fmaxf(yv.y, 0.f);
            yv.z = fmaxf(yv.z, 0.f); yv.w = fmaxf(yv.w, 0.f);
        }
        if (round_out) {
            yv.x = tfb(yv.x); yv.y = tfb(yv.y);
            yv.z = tfb(yv.z); yv.w = tfb(yv.w);
        }
        size_t off = ((size_t)b * Cout + o) * Nlen + nn0;
        if (Ypre) *(float4*)&Ypre[off] = yv;
        if (resid) {
            float4 rv = *(const float4*)&resid[off];
            yv.x += rv.x; yv.y += rv.y; yv.z += rv.z; yv.w += rv.w;
        }
        *(float4*)&Y[off] = yv;
    }
}

// ---------------- flash attention (tf32 mma, online softmax, split-KV) ----------------
#define FBQ 128
#define FBK 64
#define KSS 72
#define VSS 80
#define PSS 80

__global__ void __launch_bounds__(256, 3)
flash_attn_mma(const float* __restrict__ Q, const float* __restrict__ K,
               const float* __restrict__ V, const float* __restrict__ maskLogits,
               float* __restrict__ O,
               float* __restrict__ Opart, float* __restrict__ Mpart, float* __restrict__ Lpart,
               int Nq, int Nk, int nsplit, int kvchunk)
{
    __shared__ float ks[DHH][KSS];
    __shared__ float vB[DHH][VSS];
    __shared__ __align__(16) float ps[8][16][PSS];
    __shared__ float ms[FBK];

    const int bh = blockIdx.y;
    const int b  = bh / HH;
    const int h  = bh % HH;
    const int q0 = blockIdx.x * FBQ;
    const int sp = blockIdx.z;
    const int tid = threadIdx.x;
    const int w = tid >> 5, lane = tid & 31;
    const int g = lane >> 2, t4 = lane & 3;
    const float sm_scale = 0.17677669529663687f;  // 1/sqrt(32)
    const float MASKV = -1.0e6f * 0.17677669529663687f;

    const float* Qb = Q + ((size_t)b * CC + h * DHH) * Nq;
    const float* Kb = K + ((size_t)b * CC + h * DHH) * Nk;
    const float* Vb = V + ((size_t)b * CC + h * DHH) * Nk;

    float* qbuf = &ps[0][0][0];
    for (int i = tid; i < DHH * (FBQ / 4); i += 256) {
        int d  = i / (FBQ / 4);
        int r4 = (i % (FBQ / 4)) * 4;
        int nn = q0 + r4;
        float4 qv = make_float4(0.f, 0.f, 0.f, 0.f);
        if (nn + 3 < Nq) qv = *(const float4*)&Qb[(size_t)d * Nq + nn];
        else {
            if (nn + 0 < Nq) qv.x = Qb[(size_t)d * Nq + nn + 0];
            if (nn + 1 < Nq) qv.y = Qb[(size_t)d * Nq + nn + 1];
            if (nn + 2 < Nq) qv.z = Qb[(size_t)d * Nq + nn + 2];
        }
        *(float4*)&qbuf[d * FBQ + r4] = qv;
    }
    __syncthreads();

    uint32_t aq[4][4];
    const int qr = w * 16;
#pragma unroll
    for (int s = 0; s < 4; s++) {
        aq[s][0] = __float_as_uint(qbuf[(s * 8 + t4) * FBQ + qr + g]);
        aq[s][1] = __float_as_uint(qbuf[(s * 8 + t4) * FBQ + qr + g + 8]);
        aq[s][2] = __float_as_uint(qbuf[(s * 8 + t4 + 4) * FBQ + qr + g]);
        aq[s][3] = __float_as_uint(qbuf[(s * 8 + t4 + 4) * FBQ + qr + g + 8]);
    }

    float o[4][4];
#pragma unroll
    for (int nt = 0; nt < 4; nt++) { o[nt][0] = o[nt][1] = o[nt][2] = o[nt][3] = 0.f; }
    float m_lo = -3.0e38f, m_hi = -3.0e38f, l_lo = 0.f, l_hi = 0.f;

    const int kvbeg = sp * kvchunk;
    const int kvend = min(Nk, kvbeg + kvchunk);

    for (int k0 = kvbeg; k0 < kvend; k0 += FBK) {
        if (tid < FBK) {
            int nn = k0 + tid;
            float f;
            if (nn >= Nk)          f = 2.f;
            else if (maskLogits)   f = (maskLogits[(size_t)b * Nk + nn] > 0.f) ? 0.f : 1.f;
            else                   f = 0.f;
            ms[tid] = f;
        }
        for (int i = tid; i < DHH * (FBK / 4); i += 256) {
            int d  = i / (FBK / 4);
            int c4 = (i % (FBK / 4)) * 4;
            int nn = k0 + c4;
            float4 kv = make_float4(0.f, 0.f, 0.f, 0.f);
            float4 vv = make_float4(0.f, 0.f, 0.f, 0.f);
            if (nn < Nk) {
                kv = *(const float4*)&Kb[(size_t)d * Nk + nn];
                vv = *(const float4*)&Vb[(size_t)d * Nk + nn];
            }
            *(float4*)&ks[d][c4] = kv;
            *(float4*)&vB[d][c4] = vv;
        }
        __syncthreads();

        float sv[8][4];
#pragma unroll
        for (int nt = 0; nt < 8; nt++) {
            sv[nt][0] = sv[nt][1] = sv[nt][2] = sv[nt][3] = 0.f;
#pragma unroll
            for (int s = 0; s < 4; s++) {
                uint32_t bf[2];
                bf[0] = __float_as_uint(ks[s * 8 + t4][nt * 8 + g]);
                bf[1] = __float_as_uint(ks[s * 8 + t4 + 4][nt * 8 + g]);
                mma8(sv[nt], aq[s], bf);
            }
        }

        float tmax_lo = -3.0e38f, tmax_hi = -3.0e38f;
#pragma unroll
        for (int nt = 0; nt < 8; nt++) {
            float m0 = ms[nt * 8 + 2 * t4];
            float m1 = ms[nt * 8 + 2 * t4 + 1];
            sv[nt][0] = (m0 == 0.f) ? sv[nt][0] * sm_scale : ((m0 == 1.f) ? MASKV : -3.0e38f);
            sv[nt][1] = (m1 == 0.f) ? sv[nt][1] * sm_scale : ((m1 == 1.f) ? MASKV : -3.0e38f);
            sv[nt][2] = (m0 == 0.f) ? sv[nt][2] * sm_scale : ((m0 == 1.f) ? MASKV : -3.0e38f);
            sv[nt][3] = (m1 == 0.f) ? sv[nt][3] * sm_scale : ((m1 == 1.f) ? MASKV : -3.0e38f);
            tmax_lo = fmaxf(tmax_lo, fmaxf(sv[nt][0], sv[nt][1]));
            tmax_hi = fmaxf(tmax_hi, fmaxf(sv[nt][2], sv[nt][3]));
        }
        tmax_lo = fmaxf(tmax_lo, __shfl_xor_sync(0xffffffffu, tmax_lo, 1));
        tmax_lo = fmaxf(tmax_lo, __shfl_xor_sync(0xffffffffu, tmax_lo, 2));
        tmax_hi = fmaxf(tmax_hi, __shfl_xor_sync(0xffffffffu, tmax_hi, 1));
        tmax_hi = fmaxf(tmax_hi, __shfl_xor_sync(0xffffffffu, tmax_hi, 2));

        float mn_lo = fmaxf(m_lo, tmax_lo);
        float mn_hi = fmaxf(m_hi, tmax_hi);
        float corr_lo = __expf(m_lo - mn_lo);
        float corr_hi = __expf(m_hi - mn_hi);
        m_lo = mn_lo; m_hi = mn_hi;

        float rs_lo = 0.f, rs_hi = 0.f;
#pragma unroll
        for (int nt = 0; nt < 8; nt++) {
            float p0 = __expf(sv[nt][0] - mn_lo);
            float p1 = __expf(sv[nt][1] - mn_lo);
            float p2 = __expf(sv[nt][2] - mn_hi);
            float p3 = __expf(sv[nt][3] - mn_hi);
            rs_lo += p0 + p1;
            rs_hi += p2 + p3;
            *(float2*)&ps[w][g][nt * 8 + 2 * t4]     = make_float2(tfb(p0), tfb(p1));
            *(float2*)&ps[w][g + 8][nt * 8 + 2 * t4] = make_float2(tfb(p2), tfb(p3));
        }
        rs_lo += __shfl_xor_sync(0xffffffffu, rs_lo, 1);
        rs_lo += __shfl_xor_sync(0xffffffffu, rs_lo, 2);
        rs_hi += __shfl_xor_sync(0xffffffffu, rs_hi, 1);
        rs_hi += __shfl_xor_sync(0xffffffffu, rs_hi, 2);
        l_lo = l_lo * corr_lo + rs_lo;
        l_hi = l_hi * corr_hi + rs_hi;
#pragma unroll
        for (int nt = 0; nt < 4; nt++) {
            o[nt][0] *= corr_lo; o[nt][1] *= corr_lo;
            o[nt][2] *= corr_hi; o[nt][3] *= corr_hi;
        }
        __syncwarp();

        float4 plo[4], phi[4];
#pragma unroll
        for (int j = 0; j < 4; j++) {
            plo[j] = *(const float4*)&ps[w][g][(t4 + 4 * j) * 4];
            phi[j] = *(const float4*)&ps[w][g + 8][(t4 + 4 * j) * 4];
        }
        uint32_t ap[8][4];
#pragma unroll
        for (int s = 0; s < 8; s++) {
            int j = s >> 1, e = (s & 1) * 2;
            const float* pl = (const float*)&plo[j];
            const float* ph = (const float*)&phi[j];
            ap[s][0] = __float_as_uint(pl[e]);
            ap[s][1] = __float_as_uint(ph[e]);
            ap[s][2] = __float_as_uint(pl[e + 1]);
            ap[s][3] = __float_as_uint(ph[e + 1]);
        }
#pragma unroll
        for (int nt = 0; nt < 4; nt++) {
            float4 fv[4];
#pragma unroll
            for (int j = 0; j < 4; j++)
                fv[j] = *(const float4*)&vB[nt * 8 + g][(t4 + 4 * j) * 4];
#pragma unroll
            for (int s = 0; s < 8; s++) {
                int j = s >> 1, e = (s & 1) * 2;
                const float* vv = (const float*)&fv[j];
                uint32_t bf[2];
                bf[0] = __float_as_uint(vv[e]);
                bf[1] = __float_as_uint(vv[e + 1]);
                mma8(o[nt], ap[s], bf);
            }
        }
        __syncthreads();
    }

    const int r_lo = q0 + w * 16 + g;
    const int r_hi = r_lo + 8;
    if (nsplit == 1) {
        float* Ob = O + ((size_t)b * CC + h * DHH) * Nq;
        float il_lo = 1.f / l_lo, il_hi = 1.f / l_hi;
#pragma unroll
        for (int nt = 0; nt < 4; nt++) {
            int d0 = nt * 8 + 2 * t4;
            if (r_lo < Nq) {
                Ob[(size_t)d0 * Nq + r_lo]       = o[nt][0] * il_lo;
                Ob[(size_t)(d0 + 1) * Nq + r_lo] = o[nt][1] * il_lo;
            }
            if (r_hi < Nq) {
                Ob[(size_t)d0 * Nq + r_hi]       = o[nt][2] * il_hi;
                Ob[(size_t)(d0 + 1) * Nq + r_hi] = o[nt][3] * il_hi;
            }
        }
    } else {
        float* Op = Opart + ((size_t)sp * BH + bh) * DHH * Nq;
#pragma unroll
        for (int nt = 0; nt < 4; nt++) {
            int d0 = nt * 8 + 2 * t4;
            if (r_lo < Nq) {
                Op[(size_t)d0 * Nq + r_lo]       = o[nt][0];
                Op[(size_t)(d0 + 1) * Nq + r_lo] = o[nt][1];
            }
            if (r_hi < Nq) {
                Op[(size_t)d0 * Nq + r_hi]       = o[nt][2];
                Op[(size_t)(d0 + 1) * Nq + r_hi] = o[nt][3];
            }
        }
        if (t4 == 0) {
            size_t base = ((size_t)sp * BH + bh) * Nq;
            if (r_lo < Nq) { Mpart[base + r_lo] = m_lo; Lpart[base + r_lo] = l_lo; }
            if (r_hi < Nq) { Mpart[base + r_hi] = m_hi; Lpart[base + r_hi] = l_hi; }
        }
    }
}

__global__ void flash_combine(const float* __restrict__ Opart, const float* __restrict__ Mpart,
                              const float* __restrict__ Lpart, float* __restrict__ O,
                              int Nq, int nsplit)
{
    int idx = blockIdx.x * blockDim.x + threadIdx.x;
    if (idx >= BH * Nq) return;
    int n  = idx % Nq;
    int bh = idx / Nq;
    int b  = bh / HH;
    int h  = bh % HH;

    float M = -3.0e38f;
    for (int s = 0; s < nsplit; s++)
        M = fmaxf(M, Mpart[((size_t)s * BH + bh) * Nq + n]);
    float w[NSPLIT];
    float L = 0.f;
    for (int s = 0; s < nsplit; s++) {
        float ws = __expf(Mpart[((size_t)s * BH + bh) * Nq + n] - M);
        w[s] = ws;
        L += ws * Lpart[((size_t)s * BH + bh) * Nq + n];
    }
    float inv = 1.f / L;
    float* Ob = O + ((size_t)b * CC + h * DHH) * Nq + n;
    for (int d = 0; d < DHH; d++) {
        float acc = 0.f;
        for (int s = 0; s < nsplit; s++)
            acc += w[s] * Opart[(((size_t)s * BH + bh) * DHH + d) * Nq + n];
        Ob[(size_t)d * Nq] = acc * inv;
    }
}

// ---------------- small conv (Cout small: 16/4/1) ----------------
__global__ void conv_small(const float* __restrict__ W, const float* __restrict__ bias,
                           const float* __restrict__ X, float* __restrict__ Y,
                           int Cout, int Cin, int Nlen)
{
    int idx = blockIdx.x * blockDim.x + threadIdx.x;
    int total = BB * Cout * Nlen;
    if (idx >= total) return;
    int n = idx % Nlen;
    int o = (idx / Nlen) % Cout;
    int b = idx / (Nlen * Cout);
    float acc = bias[o];
    const float* Xb = X + (size_t)b * Cin * Nlen + n;
    const float* Wo = W + (size_t)o * Cin;
    for (int c = 0; c < Cin; c++) acc += Wo[c] * Xb[(size_t)c * Nlen];
    Y[idx] = acc;
}

// ---------------- instance norm + scale/shift + relu, in place ----------------
__global__ void instnorm_relu(float* __restrict__ X, const float* __restrict__ s,
                              const float* __restrict__ sh, int Cc, int Nlen)
{
    int bc = blockIdx.x;
    int c  = bc % Cc;
    float* x = X + (size_t)bc * Nlen;
    int tid = threadIdx.x;

    float sum = 0.f, sq = 0.f;
    for (int i = tid; i < Nlen; i += blockDim.x) { float v = x[i]; sum += v; sq += v * v; }
#pragma unroll
    for (int off = 16; off >= 1; off >>= 1) {
        sum += __shfl_xor_sync(0xffffffffu, sum, off);
        sq  += __shfl_xor_sync(0xffffffffu, sq,  off);
    }
    __shared__ float ssum[8], ssq[8];
    __shared__ float smu, sinv;
    int w = tid >> 5;
    if ((tid & 31) == 0) { ssum[w] = sum; ssq[w] = sq; }
    __syncthreads();
    if (tid == 0) {
        float S = 0.f, Q2 = 0.f;
        for (int i = 0; i < (int)(blockDim.x >> 5); i++) { S += ssum[i]; Q2 += ssq[i]; }
        float mu  = S / Nlen;
        float var = fmaxf(Q2 / Nlen - mu * mu, 0.f);
        smu  = mu;
        sinv = rsqrtf(var + 1e-3f);
    }
    __syncthreads();
    float scv = s[c] * sinv, mu = smu, shv = sh[c];
    for (int i = tid; i < Nlen; i += blockDim.x) {
        float v = (x[i] - mu) * scv + shv;
        x[i] = fmaxf(v, 0.f);
    }
}

// ---------------- host ----------------
static void run_conv(const float* WT, const float* bias,
                     const float* X1, const float* X2, int split,
                     float* Y, float* Ypre, int Cout, int Cin, int Nlen,
                     const float* scale, const float* shift, int relu,
                     const float* resid, int round_out)
{
    int gx = (Nlen + 63) / 64;
    int ctas64 = gx * (Cout / 64) * BB;
    if (ctas64 < 250 && (Cout % 32) == 0) {
        dim3 grid(gx, Cout / 32, BB);
        conv_gemm32<<<grid, 128>>>(WT, bias, X1, X2, split, Y, Ypre, Cout, Cin, Nlen,
                                   scale, shift, relu, resid, round_out);
    } else {
        dim3 grid(gx, Cout / 64, BB);
        conv_gemm<<<grid, 128>>>(WT, bias, X1, X2, split, Y, Ypre, Cout, Cin, Nlen,
                                 scale, shift, relu, resid, round_out);
    }
}

extern "C" void kernel_launch(void* const* d_in, const int* in_sizes, int n_in,
                              void* d_out, int out_size)
{
    const float* d_in1      = (const float*)d_in[1];
    const float* feat_piece = (const float*)d_in[2];
    const float* logits_in  = (const float*)d_in[3];
    const float* Wq  = (const float*)d_in[4];
    const float* bq  = (const float*)d_in[5];
    const float* Wk  = (const float*)d_in[6];
    const float* bk  = (const float*)d_in[7];
    const float* Wv  = (const float*)d_in[8];
    const float* bv  = (const float*)d_in[9];
    const float* Wm  = (const float*)d_in[10];
    const float* bm  = (const float*)d_in[11];
    const float* Wc1 = (const float*)d_in[12];
    const float* bc1 = (const float*)d_in[13];
    const float* bns = (const float*)d_in[14];
    const float* bnsh= (const float*)d_in[15];
    const float* Wc2 = (const float*)d_in[16];
    const float* bc2 = (const float*)d_in[17];
    const float* iW1 = (const float*)d_in[18];
    const float* ib1 = (const float*)d_in[19];
    const float* ibn1s  = (const float*)d_in[20];
    const float* ibn1sh = (const float*)d_in[21];
    const float* iW2 = (const float*)d_in[22];
    const float* ib2 = (const float*)d_in[23];
    const float* ibn2s  = (const float*)d_in[24];
    const float* ibn2sh = (const float*)d_in[25];
    const float* iW3 = (const float*)d_in[26];
    const float* ib3 = (const float*)d_in[27];
    const float* ibn3s  = (const float*)d_in[28];
    const float* ibn3sh = (const float*)d_in[29];
    const float* iW4 = (const float*)d_in[30];
    const float* ib4 = (const float*)d_in[31];

    float *Q, *K, *V, *AO, *Hb, *F1, *F2, *XH, *T1, *T2, *T3, *OP, *MP, *LP, *WF, *BF, *WT;
    cudaGetSymbolAddress((void**)&Q,   g_Q);
    cudaGetSymbolAddress((void**)&K,   g_K);
    cudaGetSymbolAddress((void**)&V,   g_V);
    cudaGetSymbolAddress((void**)&AO,  g_AO);
    cudaGetSymbolAddress((void**)&Hb,  g_Hb);
    cudaGetSymbolAddress((void**)&F1,  g_F1);
    cudaGetSymbolAddress((void**)&F2,  g_F2);
    cudaGetSymbolAddress((void**)&XH,  g_XH);
    cudaGetSymbolAddress((void**)&T1,  g_T1);
    cudaGetSymbolAddress((void**)&T2,  g_T2);
    cudaGetSymbolAddress((void**)&T3,  g_T3);
    cudaGetSymbolAddress((void**)&OP,  g_OP);
    cudaGetSymbolAddress((void**)&MP,  g_MP);
    cudaGetSymbolAddress((void**)&LP,  g_LP);
    cudaGetSymbolAddress((void**)&WF,  g_WF);
    cudaGetSymbolAddress((void**)&BF,  g_BF);
    cudaGetSymbolAddress((void**)&WT,  g_WT);

    // weight prep (runs every launch; deterministic)
    transpose_all<<<(WT_TOT + 255) / 256, 256>>>(Wq, Wk, Wv, Wc2, iW1, WT);
    fuse_wc1<<<(3 * 256 * 256 + 255) / 256, 256>>>(Wc1, Wm, WF);
    fuse_bc1<<<(3 * 256 + 255) / 256, 256>>>(Wc1, bc1, bm, BF);

    auto attn = [&](const float* x1, const float* x2, const float* mask,
                    int Nq, int Nk, int li, float* out, float* outPre, const float* resid) {
        const int C2 = 2 * CC;
        run_conv(WT + WT_Q + (size_t)li * CC * CC, bq + (size_t)li * CC, x1, nullptr, CC,
                 Q, nullptr, CC, CC, Nq, nullptr, nullptr, 0, nullptr, 1);
        run_conv(WT + WT_K + (size_t)li * CC * CC, bk + (size_t)li * CC, x2, nullptr, CC,
                 K, nullptr, CC, CC, Nk, nullptr, nullptr, 0, nullptr, 1);
        run_conv(WT + WT_V + (size_t)li * CC * CC, bv + (size_t)li * CC, x2, nullptr, CC,
                 V, nullptr, CC, CC, Nk, nullptr, nullptr, 0, nullptr, 1);

        int qblocks = (Nq + FBQ - 1) / FBQ;
        int nsplit  = 1;
        if (qblocks * BH < 300) nsplit = NSPLIT;
        int nkt = (Nk + FBK - 1) / FBK;
        int kvchunk = ((nkt + nsplit - 1) / nsplit) * FBK;

        dim3 fg(qblocks, BH, nsplit);
        flash_attn_mma<<<fg, 256>>>(Q, K, V, mask, AO, OP, MP, LP, Nq, Nk, nsplit, kvchunk);
        if (nsplit > 1) {
            int tot = BH * Nq;
            flash_combine<<<(tot + 255) / 256, 256>>>(OP, MP, LP, AO, Nq, nsplit);
        }

        run_conv(WF + (size_t)li * C2 * C2, BF + (size_t)li * C2, x1, AO, CC,
                 Hb, nullptr, C2, C2, Nq, bns + (size_t)li * C2, bnsh + (size_t)li * C2, 1, nullptr, 0);
        run_conv(WT + WT_C2 + (size_t)li * CC * C2, bc2 + (size_t)li * CC, Hb, nullptr, C2,
                 out, outPre, CC, C2, Nq, nullptr, nullptr, 0, resid, 0);
    };

    float* dnew   = (float*)d_out;                 // [B,C,N]
    float* logout = dnew + (size_t)BB * CC * NN;   // [B,N]

    attn(feat_piece, d_in1, logits_in, MM, NN, 0, F1, nullptr, feat_piece);
    attn(F1, F1, nullptr, MM, MM, 1, F2, nullptr, F1);
    attn(d_in1, F2, nullptr, NN, MM, 2, dnew, XH, d_in1);

    // head on x = d_new - d_old == XH
    run_conv(WT + WT_I1, ib1, XH, nullptr, CC, T1, nullptr, 64, CC, NN, nullptr, nullptr, 0, nullptr, 0);
    instnorm_relu<<<BB * 64, 256>>>(T1, ibn1s, ibn1sh, 64, NN);

    conv_small<<<(BB * 16 * NN + 255) / 256, 256>>>(iW2, ib2, T1, T2, 16, 64, NN);
    instnorm_relu<<<BB * 16, 256>>>(T2, ibn2s, ibn2sh, 16, NN);

    conv_small<<<(BB * 4 * NN + 255) / 256, 256>>>(iW3, ib3, T2, T3, 4, 16, NN);
    instnorm_relu<<<BB * 4, 256>>>(T3, ibn3s, ibn3sh, 4, NN);

    conv_small<<<(BB * 1 * NN + 255) / 256, 256>>>(iW4, ib4, T3, logout, 1, 4, NN);
}

// round 14
// speedup vs baseline: 1.6744x; 1.0631x over previous
#include <cuda_runtime.h>
#include <math.h>
#include <stdint.h>

// Problem constants
#define BB 2
#define CC 128
#define NN 6000
#define MM 1500
#define HH 4
#define DHH 32
#define BH (BB*HH)
#define NSPLIT 4

// ---------------- scratch (static device globals; no allocation) ----------------
__device__ float g_Q  [BB*CC*NN];
__device__ float g_K  [BB*CC*NN];
__device__ float g_V  [BB*CC*NN];
__device__ float g_AO [BB*CC*NN];
__device__ float g_Hb [BB*2*CC*NN];
__device__ float g_F1 [BB*CC*MM];
__device__ float g_F2 [BB*CC*MM];
__device__ float g_XH [BB*CC*NN];
__device__ float g_T1 [BB*64*NN];
__device__ float g_T2 [BB*16*NN];
__device__ float g_T3 [BB*4*NN];
// split-KV partials
__device__ float g_OP [NSPLIT*BH*DHH*NN];
__device__ float g_MP [NSPLIT*BH*NN];
__device__ float g_LP [NSPLIT*BH*NN];
// fused Wc1' (K-major): WF[l][c][o]
__device__ float g_WF [3*2*CC*2*CC];
__device__ float g_BF [3*2*CC];
// transposed weights (K-major): Wq(3),Wk(3),Wv(3) 128x128; Wc2(3) 256x128; iW1 128x64
#define WT_Q   0
#define WT_K   49152
#define WT_V   98304
#define WT_C2  147456
#define WT_I1  245760
#define WT_TOT 253952
__device__ float g_WT [WT_TOT];

// ---------------- tf32 helpers ----------------
__device__ __forceinline__ uint32_t f2tf(float f) {
    uint32_t u;
    asm("cvt.rna.tf32.f32 %0, %1;" : "=r"(u) : "f"(f));
    return u;
}
__device__ __forceinline__ float tfb(float f) { return __uint_as_float(f2tf(f)); }

__device__ __forceinline__ void mma8(float* d, const uint32_t* a, const uint32_t* b) {
    asm volatile("mma.sync.aligned.m16n8k8.row.col.f32.tf32.tf32.f32 "
                 "{%0,%1,%2,%3}, {%4,%5,%6,%7}, {%8,%9}, {%0,%1,%2,%3};\n"
                 : "+f"(d[0]), "+f"(d[1]), "+f"(d[2]), "+f"(d[3])
                 : "r"(a[0]), "r"(a[1]), "r"(a[2]), "r"(a[3]),
                   "r"(b[0]), "r"(b[1]));
}

__device__ __forceinline__ uint32_t smem_u32(const void* p) {
    uint32_t a;
    asm("{ .reg .u64 t; cvta.to.shared.u64 t, %1; cvt.u32.u64 %0, t; }" : "=r"(a) : "l"(p));
    return a;
}
__device__ __forceinline__ void cp16(uint32_t dst, const void* src, uint32_t ssz) {
    asm volatile("cp.async.ca.shared.global [%0], [%1], 16, %2;"
                 :: "r"(dst), "l"(src), "r"(ssz));
}

// ---------------- weight prep kernels ----------------
__global__ void transpose_all(const float* __restrict__ Wq, const float* __restrict__ Wk,
                              const float* __restrict__ Wv, const float* __restrict__ Wc2,
                              const float* __restrict__ iW1, float* __restrict__ WT)
{
    int idx = blockIdx.x * blockDim.x + threadIdx.x;
    if (idx >= WT_TOT) return;
    float v;
    if (idx < WT_C2) {
        int seg = idx / 49152;
        int r   = idx % 49152;
        int l   = r / 16384;
        int e   = r % 16384;
        int c   = e >> 7, o = e & 127;
        const float* Wsrc = (seg == 0) ? Wq : ((seg == 1) ? Wk : Wv);
        v = Wsrc[l * 16384 + o * 128 + c];
    } else if (idx < WT_I1) {
        int r = idx - WT_C2;
        int l = r / 32768;
        int e = r % 32768;
        int c = e >> 7, o = e & 127;
        v = Wc2[l * 32768 + o * 256 + c];
    } else {
        int e = idx - WT_I1;
        int c = e >> 6, o = e & 63;
        v = iW1[o * 128 + c];
    }
    WT[idx] = v;
}

__global__ void fuse_wc1(const float* __restrict__ Wc1, const float* __restrict__ Wm,
                         float* __restrict__ WF)
{
    int idx = blockIdx.x * blockDim.x + threadIdx.x;
    if (idx >= 3 * 256 * 256) return;
    int c = idx & 255;
    int o = (idx >> 8) & 255;
    int l = idx >> 16;
    const float* Wc1l = Wc1 + (size_t)l * 256 * 256;
    float v;
    if (c < CC) {
        v = Wc1l[o * 256 + c];
    } else {
        const float* wrow = Wc1l + o * 256 + CC;
        const float* wm   = Wm + (size_t)l * CC * CC;
        int cc = c - CC;
        float acc = 0.f;
#pragma unroll 4
        for (int k = 0; k < CC; k++) acc += wrow[k] * wm[k * CC + cc];
        v = acc;
    }
    WF[(size_t)l * 65536 + c * 256 + o] = v;
}

__global__ void fuse_bc1(const float* __restrict__ Wc1, const float* __restrict__ bc1,
                         const float* __restrict__ bm, float* __restrict__ BF)
{
    int idx = blockIdx.x * blockDim.x + threadIdx.x;
    if (idx >= 3 * 256) return;
    int o = idx & 255, l = idx >> 8;
    const float* wrow = Wc1 + (size_t)l * 256 * 256 + o * 256 + CC;
    const float* bml  = bm + l * CC;
    float acc = bc1[l * 256 + o];
#pragma unroll 4
    for (int k = 0; k < CC; k++) acc += wrow[k] * bml[k];
    BF[idx] = acc;
}

// ---------------- merged QKV GEMM: 12 segments of 32 output rows ----------------
// grid: (ceil(maxN/64), 12, BB). kind = seg>>2 (0=Q,1=K,2=V); om0 = (seg&3)*32.
#define CBK 32

__global__ void __launch_bounds__(128)
qkv_gemm32(const float* __restrict__ WTq, const float* __restrict__ WTk, const float* __restrict__ WTv,
           const float* __restrict__ bq, const float* __restrict__ bk, const float* __restrict__ bv,
           const float* __restrict__ X1, const float* __restrict__ X2,
           float* __restrict__ Qo, float* __restrict__ Ko, float* __restrict__ Vo,
           int Nq, int Nk)
{
    __shared__ __align__(16) float Ws[2][CBK][32];
    __shared__ __align__(16) float Xs[2][CBK][64];

    const int seg  = blockIdx.y;
    const int kind = seg >> 2;
    const int om0  = (seg & 3) * 32;
    const int b    = blockIdx.z;
    const int n0   = blockIdx.x * 64;
    const float* WT;
    const float* bias;
    const float* X;
    float* Y;
    int Nlen;
    if (kind == 0)      { WT = WTq; bias = bq; X = X1; Y = Qo; Nlen = Nq; }
    else if (kind == 1) { WT = WTk; bias = bk; X = X2; Y = Ko; Nlen = Nk; }
    else                { WT = WTv; bias = bv; X = X2; Y = Vo; Nlen = Nk; }
    if (n0 >= Nlen) return;

    const int tid = threadIdx.x;
    const int tx  = tid & 15;
    const int ty  = tid >> 4;

    float acc[4][4];
#pragma unroll
    for (int i = 0; i < 4; i++)
#pragma unroll
        for (int j = 0; j < 4; j++) acc[i][j] = 0.f;

    auto stage = [&](int k0, int buf) {
#pragma unroll
        for (int i = tid; i < 32 * 8; i += 128) {
            int kk = i >> 3, o4 = (i & 7) * 4;
            cp16(smem_u32(&Ws[buf][kk][o4]), &WT[(size_t)(k0 + kk) * 128 + om0 + o4], 16);
        }
#pragma unroll
        for (int i = tid; i < 32 * 16; i += 128) {
            int kk = i >> 4, n4 = (i & 15) * 4;
            int n = n0 + n4;
            int nc = (n < Nlen) ? n : 0;
            cp16(smem_u32(&Xs[buf][kk][n4]),
                 &X[((size_t)b * 128 + (k0 + kk)) * Nlen + nc], (n < Nlen) ? 16u : 0u);
        }
    };

    stage(0, 0);
    asm volatile("cp.async.commit_group;");
    for (int ch = 0; ch < 4; ch++) {
        if (ch + 1 < 4) {
            stage((ch + 1) * CBK, (ch + 1) & 1);
            asm volatile("cp.async.commit_group;");
            asm volatile("cp.async.wait_group 1;");
        } else {
            asm volatile("cp.async.wait_group 0;");
        }
        __syncthreads();
        const float (*Wb)[32] = Ws[ch & 1];
        const float (*Xb)[64] = Xs[ch & 1];
#pragma unroll 8
        for (int kk = 0; kk < CBK; kk++) {
            float4 w0 = *(const float4*)&Wb[kk][ty * 4];
            float4 rx = *(const float4*)&Xb[kk][tx * 4];
            acc[0][0] += w0.x * rx.x; acc[0][1] += w0.x * rx.y; acc[0][2] += w0.x * rx.z; acc[0][3] += w0.x * rx.w;
            acc[1][0] += w0.y * rx.x; acc[1][1] += w0.y * rx.y; acc[1][2] += w0.y * rx.z; acc[1][3] += w0.y * rx.w;
            acc[2][0] += w0.z * rx.x; acc[2][1] += w0.z * rx.y; acc[2][2] += w0.z * rx.z; acc[2][3] += w0.z * rx.w;
            acc[3][0] += w0.w * rx.x; acc[3][1] += w0.w * rx.y; acc[3][2] += w0.w * rx.z; acc[3][3] += w0.w * rx.w;
        }
        __syncthreads();
    }

    const int nn0 = n0 + tx * 4;
    if (nn0 >= Nlen) return;
#pragma unroll
    for (int i = 0; i < 4; i++) {
        int o = om0 + ty * 4 + i;
        float bi = bias[o];
        float4 yv;
        yv.x = tfb(acc[i][0] + bi);
        yv.y = tfb(acc[i][1] + bi);
        yv.z = tfb(acc[i][2] + bi);
        yv.w = tfb(acc[i][3] + bi);
        *(float4*)&Y[((size_t)b * 128 + o) * Nlen + nn0] = yv;
    }
}

// ---------------- fp32 GEMM for 1x1 conv: cp.async double-buffered (64-out tile) ----------------
__global__ void __launch_bounds__(128)
conv_gemm(const float* __restrict__ WT, const float* __restrict__ bias,
          const float* __restrict__ X1, const float* __restrict__ X2, int split,
          float* __restrict__ Y, float* __restrict__ Ypre,
          int Cout, int Cin, int Nlen,
          const float* __restrict__ scale, const float* __restrict__ shift,
          int do_relu, const float* __restrict__ resid, int round_out)
{
    __shared__ __align__(16) float Ws[2][CBK][64];
    __shared__ __align__(16) float Xs[2][CBK][64];

    const int b   = blockIdx.z;
    const int om0 = blockIdx.y * 64;
    const int n0  = blockIdx.x * 64;
    const int tid = threadIdx.x;
    const int tx  = tid & 15;
    const int ty  = tid >> 4;

    float acc[8][4];
#pragma unroll
    for (int i = 0; i < 8; i++)
#pragma unroll
        for (int j = 0; j < 4; j++) acc[i][j] = 0.f;

    const int Ci2 = Cin - split;

    auto stage = [&](int k0, int buf) {
#pragma unroll
        for (int i = tid; i < 32 * 16; i += 128) {
            int kk = i >> 4, o4 = (i & 15) * 4;
            cp16(smem_u32(&Ws[buf][kk][o4]), &WT[(size_t)(k0 + kk) * Cout + om0 + o4], 16);
        }
#pragma unroll
        for (int i = tid; i < 32 * 16; i += 128) {
            int kk = i >> 4, n4 = (i & 15) * 4;
            int c = k0 + kk;
            int n = n0 + n4;
            int nc = (n < Nlen) ? n : 0;
            const float* src;
            if (c < split) src = &X1[((size_t)b * split + c) * Nlen + nc];
            else           src = &X2[((size_t)b * Ci2 + (c - split)) * Nlen + nc];
            cp16(smem_u32(&Xs[buf][kk][n4]), src, (n < Nlen) ? 16u : 0u);
        }
    };

    const int nch = Cin / CBK;
    stage(0, 0);
    asm volatile("cp.async.commit_group;");

    for (int ch = 0; ch < nch; ch++) {
        if (ch + 1 < nch) {
            stage((ch + 1) * CBK, (ch + 1) & 1);
            asm volatile("cp.async.commit_group;");
            asm volatile("cp.async.wait_group 1;");
        } else {
            asm volatile("cp.async.wait_group 0;");
        }
        __syncthreads();

        const float (*Wb)[64] = Ws[ch & 1];
        const float (*Xb)[64] = Xs[ch & 1];
#pragma unroll 8
        for (int kk = 0; kk < CBK; kk++) {
            float4 w0 = *(const float4*)&Wb[kk][ty * 8];
            float4 w1 = *(const float4*)&Wb[kk][ty * 8 + 4];
            float4 rx = *(const float4*)&Xb[kk][tx * 4];
            const float wv[8] = {w0.x, w0.y, w0.z, w0.w, w1.x, w1.y, w1.z, w1.w};
#pragma unroll
            for (int i = 0; i < 8; i++) {
                acc[i][0] += wv[i] * rx.x;
                acc[i][1] += wv[i] * rx.y;
                acc[i][2] += wv[i] * rx.z;
                acc[i][3] += wv[i] * rx.w;
            }
        }
        __syncthreads();
    }

    const int nn0 = n0 + tx * 4;
    if (nn0 >= Nlen) return;
#pragma unroll
    for (int i = 0; i < 8; i++) {
        int o = om0 + ty * 8 + i;
        if (o >= Cout) continue;
        float bi = bias  ? bias[o]  : 0.f;
        float sc = scale ? scale[o] : 1.f;
        float sh = shift ? shift[o] : 0.f;
        float4 yv;
        yv.x = (acc[i][0] + bi) * sc + sh;
        yv.y = (acc[i][1] + bi) * sc + sh;
        yv.z = (acc[i][2] + bi) * sc + sh;
        yv.w = (acc[i][3] + bi) * sc + sh;
        if (do_relu) {
            yv.x = fmaxf(yv.x, 0.f); yv.y = fmaxf(yv.y, 0.f);
            yv.z = fmaxf(yv.z, 0.f); yv.w = fmaxf(yv.w, 0.f);
        }
        if (round_out) {
            yv.x = tfb(yv.x); yv.y = tfb(yv.y);
            yv.z = tfb(yv.z); yv.w = tfb(yv.w);
        }
        size_t off = ((size_t)b * Cout + o) * Nlen + nn0;
        if (Ypre) *(float4*)&Ypre[off] = yv;
        if (resid) {
            float4 rv = *(const float4*)&resid[off];
            yv.x += rv.x; yv.y += rv.y; yv.z += rv.z; yv.w += rv.w;
        }
        *(float4*)&Y[off] = yv;
    }
}

// ---------------- 32-out-tile variant: doubles CTA count for starved launches ----------------
__global__ void __launch_bounds__(128)
conv_gemm32(const float* __restrict__ WT, const float* __restrict__ bias,
            const float* __restrict__ X1, const float* __restrict__ X2, int split,
            float* __restrict__ Y, float* __restrict__ Ypre,
            int Cout, int Cin, int Nlen,
            const float* __restrict__ scale, const float* __restrict__ shift,
            int do_relu, const float* __restrict__ resid, int round_out)
{
    __shared__ __align__(16) float Ws[2][CBK][32];
    __shared__ __align__(16) float Xs[2][CBK][64];

    const int b   = blockIdx.z;
    const int om0 = blockIdx.y * 32;
    const int n0  = blockIdx.x * 64;
    const int tid = threadIdx.x;
    const int tx  = tid & 15;
    const int ty  = tid >> 4;

    float acc[4][4];
#pragma unroll
    for (int i = 0; i < 4; i++)
#pragma unroll
        for (int j = 0; j < 4; j++) acc[i][j] = 0.f;

    const int Ci2 = Cin - split;

    auto stage = [&](int k0, int buf) {
#pragma unroll
        for (int i = tid; i < 32 * 8; i += 128) {
            int kk = i >> 3, o4 = (i & 7) * 4;
            cp16(smem_u32(&Ws[buf][kk][o4]), &WT[(size_t)(k0 + kk) * Cout + om0 + o4], 16);
        }
#pragma unroll
        for (int i = tid; i < 32 * 16; i += 128) {
            int kk = i >> 4, n4 = (i & 15) * 4;
            int c = k0 + kk;
            int n = n0 + n4;
            int nc = (n < Nlen) ? n : 0;
            const float* src;
            if (c < split) src = &X1[((size_t)b * split + c) * Nlen + nc];
            else           src = &X2[((size_t)b * Ci2 + (c - split)) * Nlen + nc];
            cp16(smem_u32(&Xs[buf][kk][n4]), src, (n < Nlen) ? 16u : 0u);
        }
    };

    const int nch = Cin / CBK;
    stage(0, 0);
    asm volatile("cp.async.commit_group;");

    for (int ch = 0; ch < nch; ch++) {
        if (ch + 1 < nch) {
            stage((ch + 1) * CBK, (ch + 1) & 1);
            asm volatile("cp.async.commit_group;");
            asm volatile("cp.async.wait_group 1;");
        } else {
            asm volatile("cp.async.wait_group 0;");
        }
        __syncthreads();

        const float (*Wb)[32] = Ws[ch & 1];
        const float (*Xb)[64] = Xs[ch & 1];
#pragma unroll 8
        for (int kk = 0; kk < CBK; kk++) {
            float4 w0 = *(const float4*)&Wb[kk][ty * 4];
            float4 rx = *(const float4*)&Xb[kk][tx * 4];
            acc[0][0] += w0.x * rx.x; acc[0][1] += w0.x * rx.y; acc[0][2] += w0.x * rx.z; acc[0][3] += w0.x * rx.w;
            acc[1][0] += w0.y * rx.x; acc[1][1] += w0.y * rx.y; acc[1][2] += w0.y * rx.z; acc[1][3] += w0.y * rx.w;
            acc[2][0] += w0.z * rx.x; acc[2][1] += w0.z * rx.y; acc[2][2] += w0.z * rx.z; acc[2][3] += w0.z * rx.w;
            acc[3][0] += w0.w * rx.x; acc[3][1] += w0.w * rx.y; acc[3][2] += w0.w * rx.z; acc[3][3] += w0.w * rx.w;
        }
        __syncthreads();
    }

    const int nn0 = n0 + tx * 4;
    if (nn0 >= Nlen) return;
#pragma unroll
    for (int i = 0; i < 4; i++) {
        int o = om0 + ty * 4 + i;
        if (o >= Cout) continue;
        float bi = bias  ? bias[o]  : 0.f;
        float sc = scale ? scale[o] : 1.f;
        float sh = shift ? shift[o] : 0.f;
        float4 yv;
        yv.x = (acc[i][0] + bi) * sc + sh;
        yv.y = (acc[i][1] + bi) * sc + sh;
        yv.z = (acc[i][2] + bi) * sc + sh;
        yv.w = (acc[i][3] + bi) * sc + sh;
        if (do_relu) {
            yv.x = fmaxf(yv.x, 0.f); yv.y = fmaxf(yv.y, 0.f);
            yv.z = fmaxf(yv.z, 0.f); yv.w = fmaxf(yv.w, 0.f);
        }
        if (round_out) {
            yv.x = tfb(yv.x); yv.y = tfb(yv.y);
            yv.z = tfb(yv.z); yv.w = tfb(yv.w);
        }
        size_t off = ((size_t)b * Cout + o) * Nlen + nn0;
        if (Ypre) *(float4*)&Ypre[off] = yv;
        if (resid) {
            float4 rv = *(const float4*)&resid[off];
            yv.x += rv.x; yv.y += rv.y; yv.z += rv.z; yv.w += rv.w;
        }
        *(float4*)&Y[off] = yv;
    }
}

// ---------------- flash attention (tf32 mma, online softmax, split-KV) ----------------
#define FBQ 128
#define FBK 64
#define KSS 72
#define VSS 80
#define PSS 80

__global__ void __launch_bounds__(256, 3)
flash_attn_mma(const float* __restrict__ Q, const float* __restrict__ K,
               const float* __restrict__ V, const float* __restrict__ maskLogits,
               float* __restrict__ O,
               float* __restrict__ Opart, float* __restrict__ Mpart, float* __restrict__ Lpart,
               int Nq, int Nk, int nsplit, int kvchunk)
{
    __shared__ float ks[DHH][KSS];
    __shared__ float vB[DHH][VSS];
    __shared__ __align__(16) float ps[8][16][PSS];
    __shared__ float ms[FBK];

    const int bh = blockIdx.y;
    const int b  = bh / HH;
    const int h  = bh % HH;
    const int q0 = blockIdx.x * FBQ;
    const int sp = blockIdx.z;
    const int tid = threadIdx.x;
    const int w = tid >> 5, lane = tid & 31;
    const int g = lane >> 2, t4 = lane & 3;
    const float sm_scale = 0.17677669529663687f;  // 1/sqrt(32)
    const float MASKV = -1.0e6f * 0.17677669529663687f;

    const float* Qb = Q + ((size_t)b * CC + h * DHH) * Nq;
    const float* Kb = K + ((size_t)b * CC + h * DHH) * Nk;
    const float* Vb = V + ((size_t)b * CC + h * DHH) * Nk;

    float* qbuf = &ps[0][0][0];
    for (int i = tid; i < DHH * (FBQ / 4); i += 256) {
        int d  = i / (FBQ / 4);
        int r4 = (i % (FBQ / 4)) * 4;
        int nn = q0 + r4;
        float4 qv = make_float4(0.f, 0.f, 0.f, 0.f);
        if (nn + 3 < Nq) qv = *(const float4*)&Qb[(size_t)d * Nq + nn];
        else {
            if (nn + 0 < Nq) qv.x = Qb[(size_t)d * Nq + nn + 0];
            if (nn + 1 < Nq) qv.y = Qb[(size_t)d * Nq + nn + 1];
            if (nn + 2 < Nq) qv.z = Qb[(size_t)d * Nq + nn + 2];
        }
        *(float4*)&qbuf[d * FBQ + r4] = qv;
    }
    __syncthreads();

    uint32_t aq[4][4];
    const int qr = w * 16;
#pragma unroll
    for (int s = 0; s < 4; s++) {
        aq[s][0] = __float_as_uint(qbuf[(s * 8 + t4) * FBQ + qr + g]);
        aq[s][1] = __float_as_uint(qbuf[(s * 8 + t4) * FBQ + qr + g + 8]);
        aq[s][2] = __float_as_uint(qbuf[(s * 8 + t4 + 4) * FBQ + qr + g]);
        aq[s][3] = __float_as_uint(qbuf[(s * 8 + t4 + 4) * FBQ + qr + g + 8]);
    }

    float o[4][4];
#pragma unroll
    for (int nt = 0; nt < 4; nt++) { o[nt][0] = o[nt][1] = o[nt][2] = o[nt][3] = 0.f; }
    float m_lo = -3.0e38f, m_hi = -3.0e38f, l_lo = 0.f, l_hi = 0.f;

    const int kvbeg = sp * kvchunk;
    const int kvend = min(Nk, kvbeg + kvchunk);

    for (int k0 = kvbeg; k0 < kvend; k0 += FBK) {
        if (tid < FBK) {
            int nn = k0 + tid;
            float f;
            if (nn >= Nk)          f = 2.f;
            else if (maskLogits)   f = (maskLogits[(size_t)b * Nk + nn] > 0.f) ? 0.f : 1.f;
            else                   f = 0.f;
            ms[tid] = f;
        }
        for (int i = tid; i < DHH * (FBK / 4); i += 256) {
            int d  = i / (FBK / 4);
            int c4 = (i % (FBK / 4)) * 4;
            int nn = k0 + c4;
            float4 kv = make_float4(0.f, 0.f, 0.f, 0.f);
            float4 vv = make_float4(0.f, 0.f, 0.f, 0.f);
            if (nn < Nk) {
                kv = *(const float4*)&Kb[(size_t)d * Nk + nn];
                vv = *(const float4*)&Vb[(size_t)d * Nk + nn];
            }
            *(float4*)&ks[d][c4] = kv;
            *(float4*)&vB[d][c4] = vv;
        }
        __syncthreads();

        float sv[8][4];
#pragma unroll
        for (int nt = 0; nt < 8; nt++) {
            sv[nt][0] = sv[nt][1] = sv[nt][2] = sv[nt][3] = 0.f;
#pragma unroll
            for (int s = 0; s < 4; s++) {
                uint32_t bf[2];
                bf[0] = __float_as_uint(ks[s * 8 + t4][nt * 8 + g]);
                bf[1] = __float_as_uint(ks[s * 8 + t4 + 4][nt * 8 + g]);
                mma8(sv[nt], aq[s], bf);
            }
        }

        float tmax_lo = -3.0e38f, tmax_hi = -3.0e38f;
#pragma unroll
        for (int nt = 0; nt < 8; nt++) {
            float m0 = ms[nt * 8 + 2 * t4];
            float m1 = ms[nt * 8 + 2 * t4 + 1];
            sv[nt][0] = (m0 == 0.f) ? sv[nt][0] * sm_scale : ((m0 == 1.f) ? MASKV : -3.0e38f);
            sv[nt][1] = (m1 == 0.f) ? sv[nt][1] * sm_scale : ((m1 == 1.f) ? MASKV : -3.0e38f);
            sv[nt][2] = (m0 == 0.f) ? sv[nt][2] * sm_scale : ((m0 == 1.f) ? MASKV : -3.0e38f);
            sv[nt][3] = (m1 == 0.f) ? sv[nt][3] * sm_scale : ((m1 == 1.f) ? MASKV : -3.0e38f);
            tmax_lo = fmaxf(tmax_lo, fmaxf(sv[nt][0], sv[nt][1]));
            tmax_hi = fmaxf(tmax_hi, fmaxf(sv[nt][2], sv[nt][3]));
        }
        tmax_lo = fmaxf(tmax_lo, __shfl_xor_sync(0xffffffffu, tmax_lo, 1));
        tmax_lo = fmaxf(tmax_lo, __shfl_xor_sync(0xffffffffu, tmax_lo, 2));
        tmax_hi = fmaxf(tmax_hi, __shfl_xor_sync(0xffffffffu, tmax_hi, 1));
        tmax_hi = fmaxf(tmax_hi, __shfl_xor_sync(0xffffffffu, tmax_hi, 2));

        float mn_lo = fmaxf(m_lo, tmax_lo);
        float mn_hi = fmaxf(m_hi, tmax_hi);
        float corr_lo = __expf(m_lo - mn_lo);
        float corr_hi = __expf(m_hi - mn_hi);
        m_lo = mn_lo; m_hi = mn_hi;

        float rs_lo = 0.f, rs_hi = 0.f;
#pragma unroll
        for (int nt = 0; nt < 8; nt++) {
            float p0 = __expf(sv[nt][0] - mn_lo);
            float p1 = __expf(sv[nt][1] - mn_lo);
            float p2 = __expf(sv[nt][2] - mn_hi);
            float p3 = __expf(sv[nt][3] - mn_hi);
            rs_lo += p0 + p1;
            rs_hi += p2 + p3;
            *(float2*)&ps[w][g][nt * 8 + 2 * t4]     = make_float2(tfb(p0), tfb(p1));
            *(float2*)&ps[w][g + 8][nt * 8 + 2 * t4] = make_float2(tfb(p2), tfb(p3));
        }
        rs_lo += __shfl_xor_sync(0xffffffffu, rs_lo, 1);
        rs_lo += __shfl_xor_sync(0xffffffffu, rs_lo, 2);
        rs_hi += __shfl_xor_sync(0xffffffffu, rs_hi, 1);
        rs_hi += __shfl_xor_sync(0xffffffffu, rs_hi, 2);
        l_lo = l_lo * corr_lo + rs_lo;
        l_hi = l_hi * corr_hi + rs_hi;
#pragma unroll
        for (int nt = 0; nt < 4; nt++) {
            o[nt][0] *= corr_lo; o[nt][1] *= corr_lo;
            o[nt][2] *= corr_hi; o[nt][3] *= corr_hi;
        }
        __syncwarp();

        float4 plo[4], phi[4];
#pragma unroll
        for (int j = 0; j < 4; j++) {
            plo[j] = *(const float4*)&ps[w][g][(t4 + 4 * j) * 4];
            phi[j] = *(const float4*)&ps[w][g + 8][(t4 + 4 * j) * 4];
        }
        uint32_t ap[8][4];
#pragma unroll
        for (int s = 0; s < 8; s++) {
            int j = s >> 1, e = (s & 1) * 2;
            const float* pl = (const float*)&plo[j];
            const float* ph = (const float*)&phi[j];
            ap[s][0] = __float_as_uint(pl[e]);
            ap[s][1] = __float_as_uint(ph[e]);
            ap[s][2] = __float_as_uint(pl[e + 1]);
            ap[s][3] = __float_as_uint(ph[e + 1]);
        }
#pragma unroll
        for (int nt = 0; nt < 4; nt++) {
            float4 fv[4];
#pragma unroll
            for (int j = 0; j < 4; j++)
                fv[j] = *(const float4*)&vB[nt * 8 + g][(t4 + 4 * j) * 4];
#pragma unroll
            for (int s = 0; s < 8; s++) {
                int j = s >> 1, e = (s & 1) * 2;
                const float* vv = (const float*)&fv[j];
                uint32_t bf[2];
                bf[0] = __float_as_uint(vv[e]);
                bf[1] = __float_as_uint(vv[e + 1]);
                mma8(o[nt], ap[s], bf);
            }
        }
        __syncthreads();
    }

    const int r_lo = q0 + w * 16 + g;
    const int r_hi = r_lo + 8;
    if (nsplit == 1) {
        float* Ob = O + ((size_t)b * CC + h * DHH) * Nq;
        float il_lo = 1.f / l_lo, il_hi = 1.f / l_hi;
#pragma unroll
        for (int nt = 0; nt < 4; nt++) {
            int d0 = nt * 8 + 2 * t4;
            if (r_lo < Nq) {
                Ob[(size_t)d0 * Nq + r_lo]       = o[nt][0] * il_lo;
                Ob[(size_t)(d0 + 1) * Nq + r_lo] = o[nt][1] * il_lo;
            }
            if (r_hi < Nq) {
                Ob[(size_t)d0 * Nq + r_hi]       = o[nt][2] * il_hi;
                Ob[(size_t)(d0 + 1) * Nq + r_hi] = o[nt][3] * il_hi;
            }
        }
    } else {
        float* Op = Opart + ((size_t)sp * BH + bh) * DHH * Nq;
#pragma unroll
        for (int nt = 0; nt < 4; nt++) {
            int d0 = nt * 8 + 2 * t4;
            if (r_lo < Nq) {
                Op[(size_t)d0 * Nq + r_lo]       = o[nt][0];
                Op[(size_t)(d0 + 1) * Nq + r_lo] = o[nt][1];
            }
            if (r_hi < Nq) {
                Op[(size_t)d0 * Nq + r_hi]       = o[nt][2];
                Op[(size_t)(d0 + 1) * Nq + r_hi] = o[nt][3];
            }
        }
        if (t4 == 0) {
            size_t base = ((size_t)sp * BH + bh) * Nq;
            if (r_lo < Nq) { Mpart[base + r_lo] = m_lo; Lpart[base + r_lo] = l_lo; }
            if (r_hi < Nq) { Mpart[base + r_hi] = m_hi; Lpart[base + r_hi] = l_hi; }
        }
    }
}

__global__ void flash_combine(const float* __restrict__ Opart, const float* __restrict__ Mpart,
                              const float* __restrict__ Lpart, float* __restrict__ O,
                              int Nq, int nsplit)
{
    int idx = blockIdx.x * blockDim.x + threadIdx.x;
    if (idx >= BH * Nq) return;
    int n  = idx % Nq;
    int bh = idx / Nq;
    int b  = bh / HH;
    int h  = bh % HH;

    float M = -3.0e38f;
    for (int s = 0; s < nsplit; s++)
        M = fmaxf(M, Mpart[((size_t)s * BH + bh) * Nq + n]);
    float w[NSPLIT];
    float L = 0.f;
    for (int s = 0; s < nsplit; s++) {
        float ws = __expf(Mpart[((size_t)s * BH + bh) * Nq + n] - M);
        w[s] = ws;
        L += ws * Lpart[((size_t)s * BH + bh) * Nq + n];
    }
    float inv = 1.f / L;
    float* Ob = O + ((size_t)b * CC + h * DHH) * Nq + n;
    for (int d = 0; d < DHH; d++) {
        float acc = 0.f;
        for (int s = 0; s < nsplit; s++)
            acc += w[s] * Opart[(((size_t)s * BH + bh) * DHH + d) * Nq + n];
        Ob[(size_t)d * Nq] = acc * inv;
    }
}

// ---------------- small conv (Cout small: 16/4/1) ----------------
__global__ void conv_small(const float* __restrict__ W, const float* __restrict__ bias,
                           const float* __restrict__ X, float* __restrict__ Y,
                           int Cout, int Cin, int Nlen)
{
    int idx = blockIdx.x * blockDim.x + threadIdx.x;
    int total = BB * Cout * Nlen;
    if (idx >= total) return;
    int n = idx % Nlen;
    int o = (idx / Nlen) % Cout;
    int b = idx / (Nlen * Cout);
    float acc = bias[o];
    const float* Xb = X + (size_t)b * Cin * Nlen + n;
    const float* Wo = W + (size_t)o * Cin;
    for (int c = 0; c < Cin; c++) acc += Wo[c] * Xb[(size_t)c * Nlen];
    Y[idx] = acc;
}

// ---------------- instance norm + scale/shift + relu, in place ----------------
__global__ void instnorm_relu(float* __restrict__ X, const float* __restrict__ s,
                              const float* __restrict__ sh, int Cc, int Nlen)
{
    int bc = blockIdx.x;
    int c  = bc % Cc;
    float* x = X + (size_t)bc * Nlen;
    int tid = threadIdx.x;

    float sum = 0.f, sq = 0.f;
    for (int i = tid; i < Nlen; i += blockDim.x) { float v = x[i]; sum += v; sq += v * v; }
#pragma unroll
    for (int off = 16; off >= 1; off >>= 1) {
        sum += __shfl_xor_sync(0xffffffffu, sum, off);
        sq  += __shfl_xor_sync(0xffffffffu, sq,  off);
    }
    __shared__ float ssum[8], ssq[8];
    __shared__ float smu, sinv;
    int w = tid >> 5;
    if ((tid & 31) == 0) { ssum[w] = sum; ssq[w] = sq; }
    __syncthreads();
    if (tid == 0) {
        float S = 0.f, Q2 = 0.f;
        for (int i = 0; i < (int)(blockDim.x >> 5); i++) { S += ssum[i]; Q2 += ssq[i]; }
        float mu  = S / Nlen;
        float var = fmaxf(Q2 / Nlen - mu * mu, 0.f);
        smu  = mu;
        sinv = rsqrtf(var + 1e-3f);
    }
    __syncthreads();
    float scv = s[c] * sinv, mu = smu, shv = sh[c];
    for (int i = tid; i < Nlen; i += blockDim.x) {
        float v = (x[i] - mu) * scv + shv;
        x[i] = fmaxf(v, 0.f);
    }
}

// ---------------- host ----------------
static void run_conv(const float* WT, const float* bias,
                     const float* X1, const float* X2, int split,
                     float* Y, float* Ypre, int Cout, int Cin, int Nlen,
                     const float* scale, const float* shift, int relu,
                     const float* resid, int round_out)
{
    int gx = (Nlen + 63) / 64;
    int ctas64 = gx * (Cout / 64) * BB;
    if (ctas64 < 250 && (Cout % 32) == 0) {
        dim3 grid(gx, Cout / 32, BB);
        conv_gemm32<<<grid, 128>>>(WT, bias, X1, X2, split, Y, Ypre, Cout, Cin, Nlen,
                                   scale, shift, relu, resid, round_out);
    } else {
        dim3 grid(gx, Cout / 64, BB);
        conv_gemm<<<grid, 128>>>(WT, bias, X1, X2, split, Y, Ypre, Cout, Cin, Nlen,
                                 scale, shift, relu, resid, round_out);
    }
}

extern "C" void kernel_launch(void* const* d_in, const int* in_sizes, int n_in,
                              void* d_out, int out_size)
{
    const float* d_in1      = (const float*)d_in[1];
    const float* feat_piece = (const float*)d_in[2];
    const float* logits_in  = (const float*)d_in[3];
    const float* Wq  = (const float*)d_in[4];
    const float* bq  = (const float*)d_in[5];
    const float* Wk  = (const float*)d_in[6];
    const float* bk  = (const float*)d_in[7];
    const float* Wv  = (const float*)d_in[8];
    const float* bv  = (const float*)d_in[9];
    const float* Wm  = (const float*)d_in[10];
    const float* bm  = (const float*)d_in[11];
    const float* Wc1 = (const float*)d_in[12];
    const float* bc1 = (const float*)d_in[13];
    const float* bns = (const float*)d_in[14];
    const float* bnsh= (const float*)d_in[15];
    const float* Wc2 = (const float*)d_in[16];
    const float* bc2 = (const float*)d_in[17];
    const float* iW1 = (const float*)d_in[18];
    const float* ib1 = (const float*)d_in[19];
    const float* ibn1s  = (const float*)d_in[20];
    const float* ibn1sh = (const float*)d_in[21];
    const float* iW2 = (const float*)d_in[22];
    const float* ib2 = (const float*)d_in[23];
    const float* ibn2s  = (const float*)d_in[24];
    const float* ibn2sh = (const float*)d_in[25];
    const float* iW3 = (const float*)d_in[26];
    const float* ib3 = (const float*)d_in[27];
    const float* ibn3s  = (const float*)d_in[28];
    const float* ibn3sh = (const float*)d_in[29];
    const float* iW4 = (const float*)d_in[30];
    const float* ib4 = (const float*)d_in[31];

    float *Q, *K, *V, *AO, *Hb, *F1, *F2, *XH, *T1, *T2, *T3, *OP, *MP, *LP, *WF, *BF, *WT;
    cudaGetSymbolAddress((void**)&Q,   g_Q);
    cudaGetSymbolAddress((void**)&K,   g_K);
    cudaGetSymbolAddress((void**)&V,   g_V);
    cudaGetSymbolAddress((void**)&AO,  g_AO);
    cudaGetSymbolAddress((void**)&Hb,  g_Hb);
    cudaGetSymbolAddress((void**)&F1,  g_F1);
    cudaGetSymbolAddress((void**)&F2,  g_F2);
    cudaGetSymbolAddress((void**)&XH,  g_XH);
    cudaGetSymbolAddress((void**)&T1,  g_T1);
    cudaGetSymbolAddress((void**)&T2,  g_T2);
    cudaGetSymbolAddress((void**)&T3,  g_T3);
    cudaGetSymbolAddress((void**)&OP,  g_OP);
    cudaGetSymbolAddress((void**)&MP,  g_MP);
    cudaGetSymbolAddress((void**)&LP,  g_LP);
    cudaGetSymbolAddress((void**)&WF,  g_WF);
    cudaGetSymbolAddress((void**)&BF,  g_BF);
    cudaGetSymbolAddress((void**)&WT,  g_WT);

    // weight prep (runs every launch; deterministic)
    transpose_all<<<(WT_TOT + 255) / 256, 256>>>(Wq, Wk, Wv, Wc2, iW1, WT);
    fuse_wc1<<<(3 * 256 * 256 + 255) / 256, 256>>>(Wc1, Wm, WF);
    fuse_bc1<<<(3 * 256 + 255) / 256, 256>>>(Wc1, bc1, bm, BF);

    auto attn = [&](const float* x1, const float* x2, const float* mask,
                    int Nq, int Nk, int li, float* out, float* outPre, const float* resid) {
        const int C2 = 2 * CC;
        int maxN = (Nq > Nk) ? Nq : Nk;
        dim3 qg((maxN + 63) / 64, 12, BB);
        qkv_gemm32<<<qg, 128>>>(WT + WT_Q + (size_t)li * CC * CC,
                                WT + WT_K + (size_t)li * CC * CC,
                                WT + WT_V + (size_t)li * CC * CC,
                                bq + (size_t)li * CC, bk + (size_t)li * CC, bv + (size_t)li * CC,
                                x1, x2, Q, K, V, Nq, Nk);

        int qblocks = (Nq + FBQ - 1) / FBQ;
        int nsplit  = 1;
        if (qblocks * BH < 300) nsplit = NSPLIT;
        int nkt = (Nk + FBK - 1) / FBK;
        int kvchunk = ((nkt + nsplit - 1) / nsplit) * FBK;

        dim3 fg(qblocks, BH, nsplit);
        flash_attn_mma<<<fg, 256>>>(Q, K, V, mask, AO, OP, MP, LP, Nq, Nk, nsplit, kvchunk);
        if (nsplit > 1) {
            int tot = BH * Nq;
            flash_combine<<<(tot + 255) / 256, 256>>>(OP, MP, LP, AO, Nq, nsplit);
        }

        run_conv(WF + (size_t)li * C2 * C2, BF + (size_t)li * C2, x1, AO, CC,
                 Hb, nullptr, C2, C2, Nq, bns + (size_t)li * C2, bnsh + (size_t)li * C2, 1, nullptr, 0);
        run_conv(WT + WT_C2 + (size_t)li * CC * C2, bc2 + (size_t)li * CC, Hb, nullptr, C2,
                 out, outPre, CC, C2, Nq, nullptr, nullptr, 0, resid, 0);
    };

    float* dnew   = (float*)d_out;                 // [B,C,N]
    float* logout = dnew + (size_t)BB * CC * NN;   // [B,N]

    attn(feat_piece, d_in1, logits_in, MM, NN, 0, F1, nullptr, feat_piece);
    attn(F1, F1, nullptr, MM, MM, 1, F2, nullptr, F1);
    attn(d_in1, F2, nullptr, NN, MM, 2, dnew, XH, d_in1);

    // head on x = d_new - d_old == XH
    run_conv(WT + WT_I1, ib1, XH, nullptr, CC, T1, nullptr, 64, CC, NN, nullptr, nullptr, 0, nullptr, 0);
    instnorm_relu<<<BB * 64, 256>>>(T1, ibn1s, ibn1sh, 64, NN);

    conv_small<<<(BB * 16 * NN + 255) / 256, 256>>>(iW2, ib2, T1, T2, 16, 64, NN);
    instnorm_relu<<<BB * 16, 256>>>(T2, ibn2s, ibn2sh, 16, NN);

    conv_small<<<(BB * 4 * NN + 255) / 256, 256>>>(iW3, ib3, T2, T3, 4, 16, NN);
    instnorm_relu<<<BB * 4, 256>>>(T3, ibn3s, ibn3sh, 4, NN);

    conv_small<<<(BB * 1 * NN + 255) / 256, 256>>>(iW4, ib4, T3, logout, 1, 4, NN);
}